// round 7
// baseline (speedup 1.0000x reference)
#include <cuda_runtime.h>
#include <cuda_fp16.h>
#include <cstdint>
#include <cstddef>

#define NU 150000
#define NB 75000
#define NE 1500000
#define DU 64
#define DB 128
#define HD 128

#define NBLK_U 147   // ceil(150000/1024)
#define NBLK_B 74    // ceil(75000/1024)
#define TB 586       // ceil(NB/128) tiles
#define TU 1172      // ceil(NU/128) tiles

// ---------------- scratch -----------------------------------------------------
__device__ __align__(16) __half g_uh0[(size_t)NU * HD];
__device__ __align__(16) __half g_ul0[(size_t)NU * HD];
__device__ __align__(16) __half g_uh1[(size_t)NU * HD];
__device__ __align__(16) __half g_ul1[(size_t)NU * HD];
__device__ __align__(16) __half g_bh0[(size_t)NB * HD];
__device__ __align__(16) __half g_bl0[(size_t)NB * HD];
__device__ __align__(16) __half g_bh1[(size_t)NB * HD];
__device__ __align__(16) __half g_bl1[(size_t)NB * HD];
__device__ int g_deg_u[NU];
__device__ int g_deg_b[NB];
__device__ int g_offs_u[NU + 1];
__device__ int g_offs_b[NB + 1];
__device__ int g_bsum_u[NBLK_U + 1];
__device__ int g_bsum_b[NBLK_B + 1];
__device__ int g_cur_u[NU];
__device__ int g_cur_b[NB];
__device__ int g_csr_u[NE];
__device__ int g_csr_b[NE];

__device__ __forceinline__ __half* uh(int i) { return i ? g_uh1 : g_uh0; }
__device__ __forceinline__ __half* ul(int i) { return i ? g_ul1 : g_ul0; }
__device__ __forceinline__ __half* bh(int i) { return i ? g_bh1 : g_bh0; }
__device__ __forceinline__ __half* bl(int i) { return i ? g_bl1 : g_bl0; }

// ---------------- CSR build ---------------------------------------------------
__global__ void zero_deg_kernel() {
    int i = blockIdx.x * blockDim.x + threadIdx.x;
    if (i < NU) g_deg_u[i] = 0;
    else if (i < NU + NB) g_deg_b[i - NU] = 0;
}

__global__ void deg_kernel(const int* __restrict__ src, const int* __restrict__ dst) {
    int e = blockIdx.x * blockDim.x + threadIdx.x;
    if (e < NE) {
        atomicAdd(&g_deg_u[src[e]], 1);
        atomicAdd(&g_deg_b[dst[e]], 1);
    }
}

__global__ void __launch_bounds__(1024) scan_blocks(
        const int* __restrict__ deg, int* __restrict__ offs,
        int* __restrict__ bsum, int n) {
    __shared__ int wsum[32];
    const int tid = threadIdx.x;
    int i = blockIdx.x * 1024 + tid;
    int v = (i < n) ? deg[i] : 0;
    int x = v;
#pragma unroll
    for (int o = 1; o < 32; o <<= 1) {
        int y = __shfl_up_sync(0xffffffffu, x, o);
        if ((tid & 31) >= o) x += y;
    }
    if ((tid & 31) == 31) wsum[tid >> 5] = x;
    __syncthreads();
    if (tid < 32) {
        int w = wsum[tid];
#pragma unroll
        for (int o = 1; o < 32; o <<= 1) {
            int y = __shfl_up_sync(0xffffffffu, w, o);
            if (tid >= o) w += y;
        }
        wsum[tid] = w;
    }
    __syncthreads();
    int we = (tid >= 32) ? wsum[(tid >> 5) - 1] : 0;
    int incl = x + we;
    if (i < n) offs[i] = incl - v;
    if (tid == 1023) bsum[blockIdx.x] = incl;
}

__global__ void __launch_bounds__(256) scan_small(int* __restrict__ a, int L) {
    __shared__ int wsum[8];
    const int tid = threadIdx.x;
    int v = (tid < L) ? a[tid] : 0;
    int x = v;
#pragma unroll
    for (int o = 1; o < 32; o <<= 1) {
        int y = __shfl_up_sync(0xffffffffu, x, o);
        if ((tid & 31) >= o) x += y;
    }
    if ((tid & 31) == 31) wsum[tid >> 5] = x;
    __syncthreads();
    if (tid == 0) {
        int c = 0;
#pragma unroll
        for (int w = 0; w < 8; w++) { int t = wsum[w]; wsum[w] = c; c += t; }
    }
    __syncthreads();
    int excl = x - v + wsum[tid >> 5];
    if (tid < L) a[tid] = excl;
    if (tid == L) a[L] = excl;
}

__global__ void scan_add(int* __restrict__ offs, const int* __restrict__ bsum,
                         int* __restrict__ cur, int n, int nblk) {
    int i = blockIdx.x * blockDim.x + threadIdx.x;
    if (i < n) {
        int v = offs[i] + bsum[i >> 10];
        offs[i] = v;
        cur[i] = v;
    }
    if (i == 0) offs[n] = bsum[nblk];
}

__global__ void fill_kernel(const int* __restrict__ src, const int* __restrict__ dst) {
    int e = blockIdx.x * blockDim.x + threadIdx.x;
    if (e < NE) {
        int s = src[e], d = dst[e];
        g_csr_u[atomicAdd(&g_cur_u[s], 1)] = d;
        g_csr_b[atomicAdd(&g_cur_b[d], 1)] = s;
    }
}

// ---------------- shared MMA helper --------------------------------------------
__device__ __forceinline__ void mma16816(float* d, const uint32_t* a,
                                         uint32_t b0, uint32_t b1) {
    asm volatile(
        "mma.sync.aligned.m16n8k16.row.col.f32.f16.f16.f32 "
        "{%0,%1,%2,%3}, {%4,%5,%6,%7}, {%8,%9}, {%0,%1,%2,%3};"
        : "+f"(d[0]), "+f"(d[1]), "+f"(d[2]), "+f"(d[3])
        : "r"(a[0]), "r"(a[1]), "r"(a[2]), "r"(a[3]), "r"(b0), "r"(b1));
}

#define AST 72    // fp16 k-stride for 64-wide operand buffers (4*gid+tig banks)
#define FST 136   // fp16 k-stride for 128-wide mean buffer (68 = 4 mod 32)

// ---------------- projection GEMM via mma (merged user+book) -------------------
// C[N,128] = A[N,K] @ W[K,128] + bias; split-fp16 3-product; hi/lo fp16 out.
#define SMS_BIAS 0
#define SMS_AHI  1024
#define SMS_ALO  (SMS_AHI + 128 * AST * 2)
#define SMS_BHI  (SMS_ALO + 128 * AST * 2)
#define SMS_BLO  (SMS_BHI + 128 * AST * 2)
#define SMS_TOT  (SMS_BLO + 128 * AST * 2)

__global__ void __launch_bounds__(256, 2) proj_mma(
        const float* __restrict__ user_x, const float* __restrict__ book_x,
        const float* __restrict__ upw, const float* __restrict__ upb,
        const float* __restrict__ bpw, const float* __restrict__ bpb) {
    extern __shared__ char smem[];
    const int tid = threadIdx.x;
    const int wid = tid >> 5;
    const int lane = tid & 31;

    const float* A; const float* W; const float* bias;
    __half *Ch, *Cl;
    int N, K, tile;
    if (blockIdx.x < TU) {
        A = user_x; W = upw; bias = upb; Ch = g_uh0; Cl = g_ul0;
        N = NU; K = DU; tile = blockIdx.x;
    } else {
        A = book_x; W = bpw; bias = bpb; Ch = g_bh0; Cl = g_bl0;
        N = NB; K = DB; tile = blockIdx.x - TU;
    }
    const int row0 = tile * 128;
    const int nchunks = K >> 6;

    if (tid < 128) *(float*)(smem + SMS_BIAS + tid * 4) = bias[tid];

    const int warp_r = wid >> 1;
    const int warp_c = wid & 1;
    const int gid = lane >> 2;
    const int tig = lane & 3;

    float acc[2][8][4];
#pragma unroll
    for (int t = 0; t < 2; t++)
#pragma unroll
        for (int j = 0; j < 8; j++)
#pragma unroll
            for (int q = 0; q < 4; q++) acc[t][j][q] = 0.f;

    const int a_kq = (tid & 15) * 4;
    const int a_m0 = tid >> 4;
    const int bn = tid & 127;
    const int bk0 = (tid >> 7) * 32;

#pragma unroll 1
    for (int c = 0; c < nchunks; c++) {
        __syncthreads();
        const int kc0 = c * 64;
#pragma unroll
        for (int i = 0; i < 8; i++) {
            int m = a_m0 + i * 16;
            int gr = row0 + m;
            float4 v = make_float4(0.f, 0.f, 0.f, 0.f);
            if (gr < N) v = *(const float4*)(A + (size_t)gr * K + kc0 + a_kq);
            __half2 h01 = __float22half2_rn(make_float2(v.x, v.y));
            __half2 h23 = __float22half2_rn(make_float2(v.z, v.w));
            float2 f01 = __half22float2(h01);
            float2 f23 = __half22float2(h23);
            __half2 l01 = __float22half2_rn(make_float2(v.x - f01.x, v.y - f01.y));
            __half2 l23 = __float22half2_rn(make_float2(v.z - f23.x, v.w - f23.y));
            uint32_t off = (uint32_t)(m * AST + a_kq) * 2;
            *(__half2*)(smem + SMS_AHI + off)     = h01;
            *(__half2*)(smem + SMS_AHI + off + 4) = h23;
            *(__half2*)(smem + SMS_ALO + off)     = l01;
            *(__half2*)(smem + SMS_ALO + off + 4) = l23;
        }
#pragma unroll 8
        for (int j = 0; j < 32; j++) {
            int kk = bk0 + j;
            float w = W[(size_t)(kc0 + kk) * 128 + bn];
            __half h = __float2half_rn(w);
            __half l = __float2half_rn(w - __half2float(h));
            uint32_t off = (uint32_t)(bn * AST + kk) * 2;
            *(__half*)(smem + SMS_BHI + off) = h;
            *(__half*)(smem + SMS_BLO + off) = l;
        }
        __syncthreads();

#pragma unroll
        for (int ks = 0; ks < 4; ks++) {
            const int k0 = ks * 16;
            uint32_t ahr[8], alr[8];
#pragma unroll
            for (int t = 0; t < 2; t++) {
                int r0 = warp_r * 32 + t * 16 + gid;
                uint32_t o0 = (uint32_t)(r0 * AST + k0 + tig * 2) * 2;
                uint32_t o1 = (uint32_t)((r0 + 8) * AST + k0 + tig * 2) * 2;
                ahr[t * 4 + 0] = *(const uint32_t*)(smem + SMS_AHI + o0);
                ahr[t * 4 + 1] = *(const uint32_t*)(smem + SMS_AHI + o1);
                ahr[t * 4 + 2] = *(const uint32_t*)(smem + SMS_AHI + o0 + 16);
                ahr[t * 4 + 3] = *(const uint32_t*)(smem + SMS_AHI + o1 + 16);
                alr[t * 4 + 0] = *(const uint32_t*)(smem + SMS_ALO + o0);
                alr[t * 4 + 1] = *(const uint32_t*)(smem + SMS_ALO + o1);
                alr[t * 4 + 2] = *(const uint32_t*)(smem + SMS_ALO + o0 + 16);
                alr[t * 4 + 3] = *(const uint32_t*)(smem + SMS_ALO + o1 + 16);
            }
#pragma unroll
            for (int j = 0; j < 8; j++) {
                int n = warp_c * 64 + j * 8 + gid;
                uint32_t ob = (uint32_t)(n * AST + k0 + tig * 2) * 2;
                uint32_t bh0 = *(const uint32_t*)(smem + SMS_BHI + ob);
                uint32_t bh1 = *(const uint32_t*)(smem + SMS_BHI + ob + 16);
                uint32_t bl0 = *(const uint32_t*)(smem + SMS_BLO + ob);
                uint32_t bl1 = *(const uint32_t*)(smem + SMS_BLO + ob + 16);
#pragma unroll
                for (int t = 0; t < 2; t++) {
                    mma16816(acc[t][j], ahr + t * 4, bh0, bh1);
                    mma16816(acc[t][j], ahr + t * 4, bl0, bl1);
                    mma16816(acc[t][j], alr + t * 4, bh0, bh1);
                }
            }
        }
    }

    // epilogue: + bias, NO relu, split fp16 stores
    const float* bias_s = (const float*)(smem + SMS_BIAS);
#pragma unroll
    for (int t = 0; t < 2; t++) {
        int r_lo = row0 + warp_r * 32 + t * 16 + gid;
        int r_hi = r_lo + 8;
#pragma unroll
        for (int j = 0; j < 8; j++) {
            int col = warp_c * 64 + j * 8 + tig * 2;
            float bx = bias_s[col], by = bias_s[col + 1];
            if (r_lo < N) {
                float ox = acc[t][j][0] + bx, oy = acc[t][j][1] + by;
                __half2 h = __float22half2_rn(make_float2(ox, oy));
                float2 f = __half22float2(h);
                __half2 l = __float22half2_rn(make_float2(ox - f.x, oy - f.y));
                *(__half2*)(Ch + (size_t)r_lo * 128 + col) = h;
                *(__half2*)(Cl + (size_t)r_lo * 128 + col) = l;
            }
            if (r_hi < N) {
                float ox = acc[t][j][2] + bx, oy = acc[t][j][3] + by;
                __half2 h = __float22half2_rn(make_float2(ox, oy));
                float2 f = __half22float2(h);
                __half2 l = __float22half2_rn(make_float2(ox - f.x, oy - f.y));
                *(__half2*)(Ch + (size_t)r_hi * 128 + col) = h;
                *(__half2*)(Cl + (size_t)r_hi * 128 + col) = l;
            }
        }
    }
}

// ---------------- fused gather + SAGE GEMM (both directions) -------------------
// Phase 1: CTA gathers neighbor means for its 128 dst rows -> smem (fp16, FST).
// Phase 2: out = relu([mean|X] @ [Wl;Wr] + bias); mean half 1 product, X half 3.
#define SMF_BIAS 0
#define SMF_MEAN 1024
#define SMF_AHI  (SMF_MEAN + 128 * FST * 2)
#define SMF_ALO  (SMF_AHI + 128 * AST * 2)
#define SMF_BHI  (SMF_ALO + 128 * AST * 2)
#define SMF_BLO  (SMF_BHI + 128 * AST * 2)
#define SMF_TOT  (SMF_BLO + 128 * AST * 2)

__global__ void __launch_bounds__(256, 2) sage_fused(
        int cur,
        const float* __restrict__ Wl, const float* __restrict__ Wr,
        const float* __restrict__ bias) {
    extern __shared__ char smem[];
    const int tid = threadIdx.x;
    const int wid = tid >> 5;
    const int lane = tid & 31;

    int is_user, tile;
    if (blockIdx.x < TB) { is_user = 0; tile = blockIdx.x; }
    else                 { is_user = 1; tile = blockIdx.x - TB; }

    const __half* __restrict__ gsrc = is_user ? bh(cur) : uh(cur);   // other population
    const int* __restrict__ offs    = is_user ? g_offs_u : g_offs_b;
    const int* __restrict__ idx     = is_user ? g_csr_u : g_csr_b;
    const __half* __restrict__ Xh   = is_user ? uh(cur) : bh(cur);
    const __half* __restrict__ Xl   = is_user ? ul(cur) : bl(cur);
    __half* __restrict__ Oh         = is_user ? uh(cur ^ 1) : bh(cur ^ 1);
    __half* __restrict__ Ol         = is_user ? ul(cur ^ 1) : bl(cur ^ 1);
    const int N = is_user ? NU : NB;
    const int row0 = tile * 128;

    if (tid < 128) *(float*)(smem + SMF_BIAS + tid * 4) = bias[tid];

    // ---- phase 1: gather means (warp w handles rows w*16..w*16+15)
    {
        const int c4 = lane * 4;
#pragma unroll 1
        for (int i = 0; i < 16; i++) {
            int m = wid * 16 + i;
            int gr = row0 + m;
            float ax = 0.f, ay = 0.f, az = 0.f, aw = 0.f;
            if (gr < N) {
                int s = offs[gr], e = offs[gr + 1];
                int j = s;
                for (; j + 4 <= e; j += 4) {
                    int n0 = idx[j], n1 = idx[j + 1], n2 = idx[j + 2], n3 = idx[j + 3];
                    uint2 r0 = *(const uint2*)(gsrc + (size_t)n0 * HD + c4);
                    uint2 r1 = *(const uint2*)(gsrc + (size_t)n1 * HD + c4);
                    uint2 r2 = *(const uint2*)(gsrc + (size_t)n2 * HD + c4);
                    uint2 r3 = *(const uint2*)(gsrc + (size_t)n3 * HD + c4);
#pragma unroll
                    for (int q = 0; q < 4; q++) {
                        uint2 r = (q == 0) ? r0 : (q == 1) ? r1 : (q == 2) ? r2 : r3;
                        float2 f0 = __half22float2(*(__half2*)&r.x);
                        float2 f1 = __half22float2(*(__half2*)&r.y);
                        ax += f0.x; ay += f0.y; az += f1.x; aw += f1.y;
                    }
                }
                for (; j < e; j++) {
                    uint2 r = *(const uint2*)(gsrc + (size_t)idx[j] * HD + c4);
                    float2 f0 = __half22float2(*(__half2*)&r.x);
                    float2 f1 = __half22float2(*(__half2*)&r.y);
                    ax += f0.x; ay += f0.y; az += f1.x; aw += f1.y;
                }
                float invd = 1.0f / fmaxf((float)(e - s), 1.0f);
                ax *= invd; ay *= invd; az *= invd; aw *= invd;
            }
            __half2 m01 = __float22half2_rn(make_float2(ax, ay));
            __half2 m23 = __float22half2_rn(make_float2(az, aw));
            uint32_t off = (uint32_t)(m * FST + c4) * 2;
            *(__half2*)(smem + SMF_MEAN + off)     = m01;
            *(__half2*)(smem + SMF_MEAN + off + 4) = m23;
        }
    }

    const int warp_r = wid >> 1;
    const int warp_c = wid & 1;
    const int gid = lane >> 2;
    const int tig = lane & 3;

    float acc[2][8][4];
#pragma unroll
    for (int t = 0; t < 2; t++)
#pragma unroll
        for (int j = 0; j < 8; j++)
#pragma unroll
            for (int q = 0; q < 4; q++) acc[t][j][q] = 0.f;

    const int a_kq = (tid & 15) * 4;
    const int a_m0 = tid >> 4;
    const int bn = tid & 127;
    const int bk0 = (tid >> 7) * 32;

#pragma unroll 1
    for (int c = 0; c < 4; c++) {
        __syncthreads();   // first pass: all gathers done; later: protect B reuse

        const int kg0 = c * 64;
        const bool xpart = (kg0 >= 128);
        if (xpart) {
            const int akoff = kg0 - 128;
#pragma unroll
            for (int i = 0; i < 8; i++) {
                int m = a_m0 + i * 16;
                int gr = row0 + m;
                uint2 vh = make_uint2(0u, 0u), vl = make_uint2(0u, 0u);
                if (gr < N) {
                    vh = *(const uint2*)(Xh + (size_t)gr * 128 + akoff + a_kq);
                    vl = *(const uint2*)(Xl + (size_t)gr * 128 + akoff + a_kq);
                }
                uint32_t off = (uint32_t)(m * AST + a_kq) * 2;
                *(uint2*)(smem + SMF_AHI + off) = vh;
                *(uint2*)(smem + SMF_ALO + off) = vl;
            }
        }

        const float* __restrict__ wsrc = xpart ? Wr : Wl;
        const int kb = xpart ? kg0 - 128 : kg0;
#pragma unroll 8
        for (int j = 0; j < 32; j++) {
            int kk = bk0 + j;
            float w = wsrc[(size_t)(kb + kk) * 128 + bn];
            __half h = __float2half_rn(w);
            uint32_t off = (uint32_t)(bn * AST + kk) * 2;
            *(__half*)(smem + SMF_BHI + off) = h;
            if (xpart) {
                __half l = __float2half_rn(w - __half2float(h));
                *(__half*)(smem + SMF_BLO + off) = l;
            }
        }
        __syncthreads();

#pragma unroll
        for (int ks = 0; ks < 4; ks++) {
            const int k0 = ks * 16;
            uint32_t ahr[8], alr[8];
#pragma unroll
            for (int t = 0; t < 2; t++) {
                int r0 = warp_r * 32 + t * 16 + gid;
                if (xpart) {
                    uint32_t o0 = (uint32_t)(r0 * AST + k0 + tig * 2) * 2;
                    uint32_t o1 = (uint32_t)((r0 + 8) * AST + k0 + tig * 2) * 2;
                    ahr[t * 4 + 0] = *(const uint32_t*)(smem + SMF_AHI + o0);
                    ahr[t * 4 + 1] = *(const uint32_t*)(smem + SMF_AHI + o1);
                    ahr[t * 4 + 2] = *(const uint32_t*)(smem + SMF_AHI + o0 + 16);
                    ahr[t * 4 + 3] = *(const uint32_t*)(smem + SMF_AHI + o1 + 16);
                    alr[t * 4 + 0] = *(const uint32_t*)(smem + SMF_ALO + o0);
                    alr[t * 4 + 1] = *(const uint32_t*)(smem + SMF_ALO + o1);
                    alr[t * 4 + 2] = *(const uint32_t*)(smem + SMF_ALO + o0 + 16);
                    alr[t * 4 + 3] = *(const uint32_t*)(smem + SMF_ALO + o1 + 16);
                } else {
                    uint32_t o0 = (uint32_t)(r0 * FST + kg0 + k0 + tig * 2) * 2;
                    uint32_t o1 = (uint32_t)((r0 + 8) * FST + kg0 + k0 + tig * 2) * 2;
                    ahr[t * 4 + 0] = *(const uint32_t*)(smem + SMF_MEAN + o0);
                    ahr[t * 4 + 1] = *(const uint32_t*)(smem + SMF_MEAN + o1);
                    ahr[t * 4 + 2] = *(const uint32_t*)(smem + SMF_MEAN + o0 + 16);
                    ahr[t * 4 + 3] = *(const uint32_t*)(smem + SMF_MEAN + o1 + 16);
                }
            }
#pragma unroll
            for (int j = 0; j < 8; j++) {
                int n = warp_c * 64 + j * 8 + gid;
                uint32_t ob = (uint32_t)(n * AST + k0 + tig * 2) * 2;
                uint32_t bh0 = *(const uint32_t*)(smem + SMF_BHI + ob);
                uint32_t bh1 = *(const uint32_t*)(smem + SMF_BHI + ob + 16);
                if (xpart) {
                    uint32_t bl0 = *(const uint32_t*)(smem + SMF_BLO + ob);
                    uint32_t bl1 = *(const uint32_t*)(smem + SMF_BLO + ob + 16);
#pragma unroll
                    for (int t = 0; t < 2; t++) {
                        mma16816(acc[t][j], ahr + t * 4, bh0, bh1);
                        mma16816(acc[t][j], ahr + t * 4, bl0, bl1);
                        mma16816(acc[t][j], alr + t * 4, bh0, bh1);
                    }
                } else {
#pragma unroll
                    for (int t = 0; t < 2; t++)
                        mma16816(acc[t][j], ahr + t * 4, bh0, bh1);
                }
            }
        }
    }

    // ---- epilogue: bias + relu, fp16 hi/lo stores
    const float* bias_s = (const float*)(smem + SMF_BIAS);
#pragma unroll
    for (int t = 0; t < 2; t++) {
        int r_lo = row0 + warp_r * 32 + t * 16 + gid;
        int r_hi = r_lo + 8;
#pragma unroll
        for (int j = 0; j < 8; j++) {
            int col = warp_c * 64 + j * 8 + tig * 2;
            float bx = bias_s[col], by = bias_s[col + 1];
            if (r_lo < N) {
                float ox = fmaxf(acc[t][j][0] + bx, 0.f);
                float oy = fmaxf(acc[t][j][1] + by, 0.f);
                __half2 h = __float22half2_rn(make_float2(ox, oy));
                float2 f = __half22float2(h);
                __half2 l = __float22half2_rn(make_float2(ox - f.x, oy - f.y));
                *(__half2*)(Oh + (size_t)r_lo * 128 + col) = h;
                *(__half2*)(Ol + (size_t)r_lo * 128 + col) = l;
            }
            if (r_hi < N) {
                float ox = fmaxf(acc[t][j][2] + bx, 0.f);
                float oy = fmaxf(acc[t][j][3] + by, 0.f);
                __half2 h = __float22half2_rn(make_float2(ox, oy));
                float2 f = __half22float2(h);
                __half2 l = __float22half2_rn(make_float2(ox - f.x, oy - f.y));
                *(__half2*)(Oh + (size_t)r_hi * 128 + col) = h;
                *(__half2*)(Ol + (size_t)r_hi * 128 + col) = l;
            }
        }
    }
}

// ---------------- layernorm (both populations, 1 warp / row) -------------------
__global__ void __launch_bounds__(256) ln_kernel(
        int cur,
        const float* __restrict__ ug, const float* __restrict__ ube,
        const float* __restrict__ bg, const float* __restrict__ bbe,
        float* __restrict__ out) {
    int gw   = (blockIdx.x * blockDim.x + threadIdx.x) >> 5;
    int lane = threadIdx.x & 31;
    if (gw >= NU + NB) return;

    int is_user = (gw < NU);
    int w = is_user ? gw : gw - NU;
    const __half* __restrict__ Xh = is_user ? uh(cur) : bh(cur);
    const __half* __restrict__ Xl = is_user ? ul(cur) : bl(cur);
    const float* gamma = is_user ? ug : bg;
    const float* beta  = is_user ? ube : bbe;
    float* op = out + (size_t)gw * 128;

    uint2 vh = *(const uint2*)(Xh + (size_t)w * 128 + lane * 4);
    uint2 vl = *(const uint2*)(Xl + (size_t)w * 128 + lane * 4);
    float2 h0 = __half22float2(*(__half2*)&vh.x);
    float2 h1 = __half22float2(*(__half2*)&vh.y);
    float2 l0 = __half22float2(*(__half2*)&vl.x);
    float2 l1 = __half22float2(*(__half2*)&vl.y);
    float4 v;
    v.x = h0.x + l0.x; v.y = h0.y + l0.y;
    v.z = h1.x + l1.x; v.w = h1.y + l1.y;

    float s = v.x + v.y + v.z + v.w;
#pragma unroll
    for (int o = 16; o; o >>= 1) s += __shfl_xor_sync(0xffffffffu, s, o);
    float mean = s * (1.0f / 128.0f);

    float dx = v.x - mean, dy = v.y - mean, dz = v.z - mean, dw = v.w - mean;
    float q = dx * dx + dy * dy + dz * dz + dw * dw;
#pragma unroll
    for (int o = 16; o; o >>= 1) q += __shfl_xor_sync(0xffffffffu, q, o);
    float rs = rsqrtf(q * (1.0f / 128.0f) + 1e-5f);

    float4 g  = *(const float4*)(gamma + lane * 4);
    float4 bt = *(const float4*)(beta + lane * 4);
    float4 o4;
    o4.x = dx * rs * g.x + bt.x;
    o4.y = dy * rs * g.y + bt.y;
    o4.z = dz * rs * g.z + bt.z;
    o4.w = dw * rs * g.w + bt.w;
    *(float4*)(op + lane * 4) = o4;
}

// ---------------- launch --------------------------------------------------------
extern "C" void kernel_launch(void* const* d_in, const int* in_sizes, int n_in,
                              void* d_out, int out_size) {
    const float* user_x = (const float*)d_in[0];
    const float* book_x = (const float*)d_in[1];
    const int*   esrc   = (const int*)d_in[2];
    const int*   edst   = (const int*)d_in[3];
    const float* upw    = (const float*)d_in[4];
    const float* upb    = (const float*)d_in[5];
    const float* bpw    = (const float*)d_in[6];
    const float* bpb    = (const float*)d_in[7];
    const float* Wl     = (const float*)d_in[8];
    const float* bl_    = (const float*)d_in[9];
    const float* Wr     = (const float*)d_in[10];
    const float* ug     = (const float*)d_in[11];
    const float* ube    = (const float*)d_in[12];
    const float* bg     = (const float*)d_in[13];
    const float* bbe    = (const float*)d_in[14];
    float* out = (float*)d_out;

    (void)in_sizes; (void)n_in; (void)out_size;

    cudaFuncSetAttribute(proj_mma, cudaFuncAttributeMaxDynamicSharedMemorySize, SMS_TOT);
    cudaFuncSetAttribute(sage_fused, cudaFuncAttributeMaxDynamicSharedMemorySize, SMF_TOT);

    int* d_offs_u; cudaGetSymbolAddress((void**)&d_offs_u, g_offs_u);
    int* d_offs_b; cudaGetSymbolAddress((void**)&d_offs_b, g_offs_b);
    int* d_deg_u;  cudaGetSymbolAddress((void**)&d_deg_u,  g_deg_u);
    int* d_deg_b;  cudaGetSymbolAddress((void**)&d_deg_b,  g_deg_b);
    int* d_bsum_u; cudaGetSymbolAddress((void**)&d_bsum_u, g_bsum_u);
    int* d_bsum_b; cudaGetSymbolAddress((void**)&d_bsum_b, g_bsum_b);
    int* d_cur_u;  cudaGetSymbolAddress((void**)&d_cur_u,  g_cur_u);
    int* d_cur_b;  cudaGetSymbolAddress((void**)&d_cur_b,  g_cur_b);

    // ---- CSR build ----
    zero_deg_kernel<<<(NU + NB + 255) / 256, 256>>>();
    deg_kernel<<<(NE + 255) / 256, 256>>>(esrc, edst);
    scan_blocks<<<NBLK_U, 1024>>>(d_deg_u, d_offs_u, d_bsum_u, NU);
    scan_blocks<<<NBLK_B, 1024>>>(d_deg_b, d_offs_b, d_bsum_b, NB);
    scan_small<<<1, 256>>>(d_bsum_u, NBLK_U);
    scan_small<<<1, 256>>>(d_bsum_b, NBLK_B);
    scan_add<<<(NU + 255) / 256, 256>>>(d_offs_u, d_bsum_u, d_cur_u, NU, NBLK_U);
    scan_add<<<(NB + 255) / 256, 256>>>(d_offs_b, d_bsum_b, d_cur_b, NB, NBLK_B);
    fill_kernel<<<(NE + 255) / 256, 256>>>(esrc, edst);

    // ---- projections (tensor core, merged) ----
    proj_mma<<<TU + TB, 256, SMS_TOT>>>(user_x, book_x, upw, upb, bpw, bpb);

    int cur = 0;
    for (int l = 0; l < 3; l++) {
        sage_fused<<<TB + TU, 256, SMF_TOT>>>(cur, Wl + (size_t)l * 128 * 128,
                                              Wr + (size_t)l * 128 * 128,
                                              bl_ + (size_t)l * 128);
        cur ^= 1;
    }

    ln_kernel<<<(int)(((size_t)(NU + NB) * 32 + 255) / 256), 256>>>(
        cur, ug, ube, bg, bbe, out);
}

// round 8
// speedup vs baseline: 1.3713x; 1.3713x over previous
#include <cuda_runtime.h>
#include <cuda_fp16.h>
#include <cstdint>
#include <cstddef>

#define NU 150000
#define NB 75000
#define NE 1500000
#define DU 64
#define DB 128
#define HD 128

#define NBLK_U 147   // ceil(150000/1024)
#define NBLK_B 74    // ceil(75000/1024)
#define TB 586       // ceil(NB/128) tiles
#define TU 1172      // ceil(NU/128) tiles

// ---------------- scratch -----------------------------------------------------
__device__ __align__(16) __half g_uh0[(size_t)NU * HD];
__device__ __align__(16) __half g_ul0[(size_t)NU * HD];
__device__ __align__(16) __half g_uh1[(size_t)NU * HD];
__device__ __align__(16) __half g_ul1[(size_t)NU * HD];
__device__ __align__(16) __half g_bh0[(size_t)NB * HD];
__device__ __align__(16) __half g_bl0[(size_t)NB * HD];
__device__ __align__(16) __half g_bh1[(size_t)NB * HD];
__device__ __align__(16) __half g_bl1[(size_t)NB * HD];
__device__ __align__(16) __half g_mh_u[(size_t)NU * HD];   // fp16 neighbor means
__device__ __align__(16) __half g_mh_b[(size_t)NB * HD];
__device__ int g_deg_u[NU];
__device__ int g_deg_b[NB];
__device__ int g_offs_u[NU + 1];
__device__ int g_offs_b[NB + 1];
__device__ int g_bsum_u[NBLK_U + 1];
__device__ int g_bsum_b[NBLK_B + 1];
__device__ int g_cur_u[NU];
__device__ int g_cur_b[NB];
__device__ int g_csr_u[NE];
__device__ int g_csr_b[NE];

__device__ __forceinline__ __half* uh(int i) { return i ? g_uh1 : g_uh0; }
__device__ __forceinline__ __half* ul(int i) { return i ? g_ul1 : g_ul0; }
__device__ __forceinline__ __half* bh(int i) { return i ? g_bh1 : g_bh0; }
__device__ __forceinline__ __half* bl(int i) { return i ? g_bl1 : g_bl0; }

// ---------------- CSR build ---------------------------------------------------
__global__ void zero_deg_kernel() {
    int i = blockIdx.x * blockDim.x + threadIdx.x;
    if (i < NU) g_deg_u[i] = 0;
    else if (i < NU + NB) g_deg_b[i - NU] = 0;
}

__global__ void deg_kernel(const int* __restrict__ src, const int* __restrict__ dst) {
    int e = blockIdx.x * blockDim.x + threadIdx.x;
    if (e < NE) {
        atomicAdd(&g_deg_u[src[e]], 1);
        atomicAdd(&g_deg_b[dst[e]], 1);
    }
}

__global__ void __launch_bounds__(1024) scan_blocks(
        const int* __restrict__ deg, int* __restrict__ offs,
        int* __restrict__ bsum, int n) {
    __shared__ int wsum[32];
    const int tid = threadIdx.x;
    int i = blockIdx.x * 1024 + tid;
    int v = (i < n) ? deg[i] : 0;
    int x = v;
#pragma unroll
    for (int o = 1; o < 32; o <<= 1) {
        int y = __shfl_up_sync(0xffffffffu, x, o);
        if ((tid & 31) >= o) x += y;
    }
    if ((tid & 31) == 31) wsum[tid >> 5] = x;
    __syncthreads();
    if (tid < 32) {
        int w = wsum[tid];
#pragma unroll
        for (int o = 1; o < 32; o <<= 1) {
            int y = __shfl_up_sync(0xffffffffu, w, o);
            if (tid >= o) w += y;
        }
        wsum[tid] = w;
    }
    __syncthreads();
    int we = (tid >= 32) ? wsum[(tid >> 5) - 1] : 0;
    int incl = x + we;
    if (i < n) offs[i] = incl - v;
    if (tid == 1023) bsum[blockIdx.x] = incl;
}

__global__ void __launch_bounds__(256) scan_small(int* __restrict__ a, int L) {
    __shared__ int wsum[8];
    const int tid = threadIdx.x;
    int v = (tid < L) ? a[tid] : 0;
    int x = v;
#pragma unroll
    for (int o = 1; o < 32; o <<= 1) {
        int y = __shfl_up_sync(0xffffffffu, x, o);
        if ((tid & 31) >= o) x += y;
    }
    if ((tid & 31) == 31) wsum[tid >> 5] = x;
    __syncthreads();
    if (tid == 0) {
        int c = 0;
#pragma unroll
        for (int w = 0; w < 8; w++) { int t = wsum[w]; wsum[w] = c; c += t; }
    }
    __syncthreads();
    int excl = x - v + wsum[tid >> 5];
    if (tid < L) a[tid] = excl;
    if (tid == L) a[L] = excl;
}

__global__ void scan_add(int* __restrict__ offs, const int* __restrict__ bsum,
                         int* __restrict__ cur, int n, int nblk) {
    int i = blockIdx.x * blockDim.x + threadIdx.x;
    if (i < n) {
        int v = offs[i] + bsum[i >> 10];
        offs[i] = v;
        cur[i] = v;
    }
    if (i == 0) offs[n] = bsum[nblk];
}

__global__ void fill_kernel(const int* __restrict__ src, const int* __restrict__ dst) {
    int e = blockIdx.x * blockDim.x + threadIdx.x;
    if (e < NE) {
        int s = src[e], d = dst[e];
        g_csr_u[atomicAdd(&g_cur_u[s], 1)] = d;
        g_csr_b[atomicAdd(&g_cur_b[d], 1)] = s;
    }
}

// ---------------- CSR gather (both directions, 1 warp / dst row) --------------
__global__ void __launch_bounds__(256) gather_mean(int cur) {
    int gw   = (blockIdx.x * blockDim.x + threadIdx.x) >> 5;
    int lane = threadIdx.x & 31;

    int is_user, w;
    if (gw < NB) { is_user = 0; w = gw; }
    else         { is_user = 1; w = gw - NB; if (w >= NU) return; }

    const __half* __restrict__ src = is_user ? bh(cur) : uh(cur);
    __half* __restrict__ out       = is_user ? g_mh_u : g_mh_b;
    const int* __restrict__ offs   = is_user ? g_offs_u : g_offs_b;
    const int* __restrict__ idx    = is_user ? g_csr_u : g_csr_b;

    int s = offs[w], e = offs[w + 1];
    const int c4 = lane * 4;

    float ax = 0.f, ay = 0.f, az = 0.f, aw = 0.f;
    int j = s;
    for (; j + 4 <= e; j += 4) {
        int n0 = idx[j], n1 = idx[j + 1], n2 = idx[j + 2], n3 = idx[j + 3];
        uint2 r0 = *(const uint2*)(src + (size_t)n0 * HD + c4);
        uint2 r1 = *(const uint2*)(src + (size_t)n1 * HD + c4);
        uint2 r2 = *(const uint2*)(src + (size_t)n2 * HD + c4);
        uint2 r3 = *(const uint2*)(src + (size_t)n3 * HD + c4);
#pragma unroll
        for (int q = 0; q < 4; q++) {
            uint2 r = (q == 0) ? r0 : (q == 1) ? r1 : (q == 2) ? r2 : r3;
            float2 f0 = __half22float2(*(__half2*)&r.x);
            float2 f1 = __half22float2(*(__half2*)&r.y);
            ax += f0.x; ay += f0.y; az += f1.x; aw += f1.y;
        }
    }
    for (; j < e; j++) {
        uint2 r = *(const uint2*)(src + (size_t)idx[j] * HD + c4);
        float2 f0 = __half22float2(*(__half2*)&r.x);
        float2 f1 = __half22float2(*(__half2*)&r.y);
        ax += f0.x; ay += f0.y; az += f1.x; aw += f1.y;
    }
    float invd = 1.0f / fmaxf((float)(e - s), 1.0f);
    __half2 m01 = __float22half2_rn(make_float2(ax * invd, ay * invd));
    __half2 m23 = __float22half2_rn(make_float2(az * invd, aw * invd));
    uint2 o; o.x = *(uint32_t*)&m01; o.y = *(uint32_t*)&m23;
    *(uint2*)(out + (size_t)w * HD + c4) = o;
}

// ---------------- shared MMA helper --------------------------------------------
__device__ __forceinline__ void mma16816(float* d, const uint32_t* a,
                                         uint32_t b0, uint32_t b1) {
    asm volatile(
        "mma.sync.aligned.m16n8k16.row.col.f32.f16.f16.f32 "
        "{%0,%1,%2,%3}, {%4,%5,%6,%7}, {%8,%9}, {%0,%1,%2,%3};"
        : "+f"(d[0]), "+f"(d[1]), "+f"(d[2]), "+f"(d[3])
        : "r"(a[0]), "r"(a[1]), "r"(a[2]), "r"(a[3]), "r"(b0), "r"(b1));
}

#define AST 72    // fp16 k-stride in smem (conflict-free fragment loads)
#define SMS_BIAS 0
#define SMS_AHI  1024
#define SMS_ALO  (SMS_AHI + 128 * AST * 2)
#define SMS_BHI  (SMS_ALO + 128 * AST * 2)
#define SMS_BLO  (SMS_BHI + 128 * AST * 2)
#define SMS_TOT  (SMS_BLO + 128 * AST * 2)

// ---------------- projection GEMM via mma (merged user+book) -------------------
__global__ void __launch_bounds__(256, 2) proj_mma(
        const float* __restrict__ user_x, const float* __restrict__ book_x,
        const float* __restrict__ upw, const float* __restrict__ upb,
        const float* __restrict__ bpw, const float* __restrict__ bpb) {
    extern __shared__ char smem[];
    const int tid = threadIdx.x;
    const int wid = tid >> 5;
    const int lane = tid & 31;

    const float* A; const float* W; const float* bias;
    __half *Ch, *Cl;
    int N, K, tile;
    if (blockIdx.x < TU) {
        A = user_x; W = upw; bias = upb; Ch = g_uh0; Cl = g_ul0;
        N = NU; K = DU; tile = blockIdx.x;
    } else {
        A = book_x; W = bpw; bias = bpb; Ch = g_bh0; Cl = g_bl0;
        N = NB; K = DB; tile = blockIdx.x - TU;
    }
    const int row0 = tile * 128;
    const int nchunks = K >> 6;

    if (tid < 128) *(float*)(smem + SMS_BIAS + tid * 4) = bias[tid];

    const int warp_r = wid >> 1;
    const int warp_c = wid & 1;
    const int gid = lane >> 2;
    const int tig = lane & 3;

    float acc[2][8][4];
#pragma unroll
    for (int t = 0; t < 2; t++)
#pragma unroll
        for (int j = 0; j < 8; j++)
#pragma unroll
            for (int q = 0; q < 4; q++) acc[t][j][q] = 0.f;

    const int a_kq = (tid & 15) * 4;
    const int a_m0 = tid >> 4;
    const int bn = tid & 127;
    const int bk0 = (tid >> 7) * 32;

#pragma unroll 1
    for (int c = 0; c < nchunks; c++) {
        __syncthreads();
        const int kc0 = c * 64;
#pragma unroll
        for (int i = 0; i < 8; i++) {
            int m = a_m0 + i * 16;
            int gr = row0 + m;
            float4 v = make_float4(0.f, 0.f, 0.f, 0.f);
            if (gr < N) v = *(const float4*)(A + (size_t)gr * K + kc0 + a_kq);
            __half2 h01 = __float22half2_rn(make_float2(v.x, v.y));
            __half2 h23 = __float22half2_rn(make_float2(v.z, v.w));
            float2 f01 = __half22float2(h01);
            float2 f23 = __half22float2(h23);
            __half2 l01 = __float22half2_rn(make_float2(v.x - f01.x, v.y - f01.y));
            __half2 l23 = __float22half2_rn(make_float2(v.z - f23.x, v.w - f23.y));
            uint32_t off = (uint32_t)(m * AST + a_kq) * 2;
            *(__half2*)(smem + SMS_AHI + off)     = h01;
            *(__half2*)(smem + SMS_AHI + off + 4) = h23;
            *(__half2*)(smem + SMS_ALO + off)     = l01;
            *(__half2*)(smem + SMS_ALO + off + 4) = l23;
        }
#pragma unroll 8
        for (int j = 0; j < 32; j++) {
            int kk = bk0 + j;
            float w = W[(size_t)(kc0 + kk) * 128 + bn];
            __half h = __float2half_rn(w);
            __half l = __float2half_rn(w - __half2float(h));
            uint32_t off = (uint32_t)(bn * AST + kk) * 2;
            *(__half*)(smem + SMS_BHI + off) = h;
            *(__half*)(smem + SMS_BLO + off) = l;
        }
        __syncthreads();

#pragma unroll
        for (int ks = 0; ks < 4; ks++) {
            const int k0 = ks * 16;
            uint32_t ahr[8], alr[8];
#pragma unroll
            for (int t = 0; t < 2; t++) {
                int r0 = warp_r * 32 + t * 16 + gid;
                uint32_t o0 = (uint32_t)(r0 * AST + k0 + tig * 2) * 2;
                uint32_t o1 = (uint32_t)((r0 + 8) * AST + k0 + tig * 2) * 2;
                ahr[t * 4 + 0] = *(const uint32_t*)(smem + SMS_AHI + o0);
                ahr[t * 4 + 1] = *(const uint32_t*)(smem + SMS_AHI + o1);
                ahr[t * 4 + 2] = *(const uint32_t*)(smem + SMS_AHI + o0 + 16);
                ahr[t * 4 + 3] = *(const uint32_t*)(smem + SMS_AHI + o1 + 16);
                alr[t * 4 + 0] = *(const uint32_t*)(smem + SMS_ALO + o0);
                alr[t * 4 + 1] = *(const uint32_t*)(smem + SMS_ALO + o1);
                alr[t * 4 + 2] = *(const uint32_t*)(smem + SMS_ALO + o0 + 16);
                alr[t * 4 + 3] = *(const uint32_t*)(smem + SMS_ALO + o1 + 16);
            }
#pragma unroll
            for (int j = 0; j < 8; j++) {
                int n = warp_c * 64 + j * 8 + gid;
                uint32_t ob = (uint32_t)(n * AST + k0 + tig * 2) * 2;
                uint32_t bh0 = *(const uint32_t*)(smem + SMS_BHI + ob);
                uint32_t bh1 = *(const uint32_t*)(smem + SMS_BHI + ob + 16);
                uint32_t bl0 = *(const uint32_t*)(smem + SMS_BLO + ob);
                uint32_t bl1 = *(const uint32_t*)(smem + SMS_BLO + ob + 16);
#pragma unroll
                for (int t = 0; t < 2; t++) {
                    mma16816(acc[t][j], ahr + t * 4, bh0, bh1);
                    mma16816(acc[t][j], ahr + t * 4, bl0, bl1);
                    mma16816(acc[t][j], alr + t * 4, bh0, bh1);
                }
            }
        }
    }

    // epilogue: + bias (no relu), split fp16 stores
    const float* bias_s = (const float*)(smem + SMS_BIAS);
#pragma unroll
    for (int t = 0; t < 2; t++) {
        int r_lo = row0 + warp_r * 32 + t * 16 + gid;
        int r_hi = r_lo + 8;
#pragma unroll
        for (int j = 0; j < 8; j++) {
            int col = warp_c * 64 + j * 8 + tig * 2;
            float bx = bias_s[col], by = bias_s[col + 1];
            if (r_lo < N) {
                float ox = acc[t][j][0] + bx, oy = acc[t][j][1] + by;
                __half2 h = __float22half2_rn(make_float2(ox, oy));
                float2 f = __half22float2(h);
                __half2 l = __float22half2_rn(make_float2(ox - f.x, oy - f.y));
                *(__half2*)(Ch + (size_t)r_lo * 128 + col) = h;
                *(__half2*)(Cl + (size_t)r_lo * 128 + col) = l;
            }
            if (r_hi < N) {
                float ox = acc[t][j][2] + bx, oy = acc[t][j][3] + by;
                __half2 h = __float22half2_rn(make_float2(ox, oy));
                float2 f = __half22float2(h);
                __half2 l = __float22half2_rn(make_float2(ox - f.x, oy - f.y));
                *(__half2*)(Ch + (size_t)r_hi * 128 + col) = h;
                *(__half2*)(Cl + (size_t)r_hi * 128 + col) = l;
            }
        }
    }
}

// ---------------- tensor-core SAGE GEMM (both directions in one launch) --------
// out = relu([mean|X] @ [Wl;Wr] + bias)
// mean half (chunks 0-1): Ah@Bh (mean already fp16-lossy -> 1 product)
// X half    (chunks 2-3): Ah@Bh + Ah@Bl + Al@Bh (exact split, 3 products)
__global__ void __launch_bounds__(256, 2) sage_mma(
        int cur,
        const float* __restrict__ Wl, const float* __restrict__ Wr,
        const float* __restrict__ bias) {
    extern __shared__ char smem[];
    const int tid = threadIdx.x;
    const int wid = tid >> 5;
    const int lane = tid & 31;

    int is_user, tile;
    if (blockIdx.x < TB) { is_user = 0; tile = blockIdx.x; }
    else                 { is_user = 1; tile = blockIdx.x - TB; }

    const __half* __restrict__ meanh = is_user ? g_mh_u : g_mh_b;
    const __half* __restrict__ Xh    = is_user ? uh(cur) : bh(cur);
    const __half* __restrict__ Xl    = is_user ? ul(cur) : bl(cur);
    __half* __restrict__ Oh          = is_user ? uh(cur ^ 1) : bh(cur ^ 1);
    __half* __restrict__ Ol          = is_user ? ul(cur ^ 1) : bl(cur ^ 1);
    const int N = is_user ? NU : NB;
    const int row0 = tile * 128;

    if (tid < 128) *(float*)(smem + SMS_BIAS + tid * 4) = bias[tid];

    const int warp_r = wid >> 1;
    const int warp_c = wid & 1;
    const int gid = lane >> 2;
    const int tig = lane & 3;

    float acc[2][8][4];
#pragma unroll
    for (int t = 0; t < 2; t++)
#pragma unroll
        for (int j = 0; j < 8; j++)
#pragma unroll
            for (int q = 0; q < 4; q++) acc[t][j][q] = 0.f;

    const int a_kq = (tid & 15) * 4;
    const int a_m0 = tid >> 4;
    const int bn = tid & 127;
    const int bk0 = (tid >> 7) * 32;

#pragma unroll 1
    for (int c = 0; c < 4; c++) {
        __syncthreads();

        const int kg0 = c * 64;
        const bool xpart = (kg0 >= 128);
        if (!xpart) {
            // mean chunk: fp16 hi already in global -> straight copy (no lo)
#pragma unroll
            for (int i = 0; i < 8; i++) {
                int m = a_m0 + i * 16;
                int gr = row0 + m;
                uint2 vh = make_uint2(0u, 0u);
                if (gr < N) vh = *(const uint2*)(meanh + (size_t)gr * 128 + kg0 + a_kq);
                uint32_t off = (uint32_t)(m * AST + a_kq) * 2;
                *(uint2*)(smem + SMS_AHI + off) = vh;
            }
        } else {
            const int akoff = kg0 - 128;
#pragma unroll
            for (int i = 0; i < 8; i++) {
                int m = a_m0 + i * 16;
                int gr = row0 + m;
                uint2 vh = make_uint2(0u, 0u), vl = make_uint2(0u, 0u);
                if (gr < N) {
                    vh = *(const uint2*)(Xh + (size_t)gr * 128 + akoff + a_kq);
                    vl = *(const uint2*)(Xl + (size_t)gr * 128 + akoff + a_kq);
                }
                uint32_t off = (uint32_t)(m * AST + a_kq) * 2;
                *(uint2*)(smem + SMS_AHI + off) = vh;
                *(uint2*)(smem + SMS_ALO + off) = vl;
            }
        }

        const float* __restrict__ wsrc = xpart ? Wr : Wl;
        const int kb = xpart ? kg0 - 128 : kg0;
#pragma unroll 8
        for (int j = 0; j < 32; j++) {
            int kk = bk0 + j;
            float w = wsrc[(size_t)(kb + kk) * 128 + bn];
            __half h = __float2half_rn(w);
            uint32_t off = (uint32_t)(bn * AST + kk) * 2;
            *(__half*)(smem + SMS_BHI + off) = h;
            if (xpart) {
                __half l = __float2half_rn(w - __half2float(h));
                *(__half*)(smem + SMS_BLO + off) = l;
            }
        }
        __syncthreads();

#pragma unroll
        for (int ks = 0; ks < 4; ks++) {
            const int k0 = ks * 16;
            uint32_t ahr[8], alr[8];
#pragma unroll
            for (int t = 0; t < 2; t++) {
                int r0 = warp_r * 32 + t * 16 + gid;
                uint32_t o0 = (uint32_t)(r0 * AST + k0 + tig * 2) * 2;
                uint32_t o1 = (uint32_t)((r0 + 8) * AST + k0 + tig * 2) * 2;
                ahr[t * 4 + 0] = *(const uint32_t*)(smem + SMS_AHI + o0);
                ahr[t * 4 + 1] = *(const uint32_t*)(smem + SMS_AHI + o1);
                ahr[t * 4 + 2] = *(const uint32_t*)(smem + SMS_AHI + o0 + 16);
                ahr[t * 4 + 3] = *(const uint32_t*)(smem + SMS_AHI + o1 + 16);
                if (xpart) {
                    alr[t * 4 + 0] = *(const uint32_t*)(smem + SMS_ALO + o0);
                    alr[t * 4 + 1] = *(const uint32_t*)(smem + SMS_ALO + o1);
                    alr[t * 4 + 2] = *(const uint32_t*)(smem + SMS_ALO + o0 + 16);
                    alr[t * 4 + 3] = *(const uint32_t*)(smem + SMS_ALO + o1 + 16);
                }
            }
#pragma unroll
            for (int j = 0; j < 8; j++) {
                int n = warp_c * 64 + j * 8 + gid;
                uint32_t ob = (uint32_t)(n * AST + k0 + tig * 2) * 2;
                uint32_t bh0 = *(const uint32_t*)(smem + SMS_BHI + ob);
                uint32_t bh1 = *(const uint32_t*)(smem + SMS_BHI + ob + 16);
                if (xpart) {
                    uint32_t bl0 = *(const uint32_t*)(smem + SMS_BLO + ob);
                    uint32_t bl1 = *(const uint32_t*)(smem + SMS_BLO + ob + 16);
#pragma unroll
                    for (int t = 0; t < 2; t++) {
                        mma16816(acc[t][j], ahr + t * 4, bh0, bh1);
                        mma16816(acc[t][j], ahr + t * 4, bl0, bl1);
                        mma16816(acc[t][j], alr + t * 4, bh0, bh1);
                    }
                } else {
#pragma unroll
                    for (int t = 0; t < 2; t++)
                        mma16816(acc[t][j], ahr + t * 4, bh0, bh1);
                }
            }
        }
    }

    // ---- epilogue: bias + relu, fp16 hi/lo stores
    const float* bias_s = (const float*)(smem + SMS_BIAS);
#pragma unroll
    for (int t = 0; t < 2; t++) {
        int r_lo = row0 + warp_r * 32 + t * 16 + gid;
        int r_hi = r_lo + 8;
#pragma unroll
        for (int j = 0; j < 8; j++) {
            int col = warp_c * 64 + j * 8 + tig * 2;
            float bx = bias_s[col], by = bias_s[col + 1];
            if (r_lo < N) {
                float ox = fmaxf(acc[t][j][0] + bx, 0.f);
                float oy = fmaxf(acc[t][j][1] + by, 0.f);
                __half2 h = __float22half2_rn(make_float2(ox, oy));
                float2 f = __half22float2(h);
                __half2 l = __float22half2_rn(make_float2(ox - f.x, oy - f.y));
                *(__half2*)(Oh + (size_t)r_lo * 128 + col) = h;
                *(__half2*)(Ol + (size_t)r_lo * 128 + col) = l;
            }
            if (r_hi < N) {
                float ox = fmaxf(acc[t][j][2] + bx, 0.f);
                float oy = fmaxf(acc[t][j][3] + by, 0.f);
                __half2 h = __float22half2_rn(make_float2(ox, oy));
                float2 f = __half22float2(h);
                __half2 l = __float22half2_rn(make_float2(ox - f.x, oy - f.y));
                *(__half2*)(Oh + (size_t)r_hi * 128 + col) = h;
                *(__half2*)(Ol + (size_t)r_hi * 128 + col) = l;
            }
        }
    }
}

// ---------------- layernorm (both populations, 1 warp / row) -------------------
__global__ void __launch_bounds__(256) ln_kernel(
        int cur,
        const float* __restrict__ ug, const float* __restrict__ ube,
        const float* __restrict__ bg, const float* __restrict__ bbe,
        float* __restrict__ out) {
    int gw   = (blockIdx.x * blockDim.x + threadIdx.x) >> 5;
    int lane = threadIdx.x & 31;
    if (gw >= NU + NB) return;

    int is_user = (gw < NU);
    int w = is_user ? gw : gw - NU;
    const __half* __restrict__ Xh = is_user ? uh(cur) : bh(cur);
    const __half* __restrict__ Xl = is_user ? ul(cur) : bl(cur);
    const float* gamma = is_user ? ug : bg;
    const float* beta  = is_user ? ube : bbe;
    float* op = out + (size_t)gw * 128;

    uint2 vh = *(const uint2*)(Xh + (size_t)w * 128 + lane * 4);
    uint2 vl = *(const uint2*)(Xl + (size_t)w * 128 + lane * 4);
    float2 h0 = __half22float2(*(__half2*)&vh.x);
    float2 h1 = __half22float2(*(__half2*)&vh.y);
    float2 l0 = __half22float2(*(__half2*)&vl.x);
    float2 l1 = __half22float2(*(__half2*)&vl.y);
    float4 v;
    v.x = h0.x + l0.x; v.y = h0.y + l0.y;
    v.z = h1.x + l1.x; v.w = h1.y + l1.y;

    float s = v.x + v.y + v.z + v.w;
#pragma unroll
    for (int o = 16; o; o >>= 1) s += __shfl_xor_sync(0xffffffffu, s, o);
    float mean = s * (1.0f / 128.0f);

    float dx = v.x - mean, dy = v.y - mean, dz = v.z - mean, dw = v.w - mean;
    float q = dx * dx + dy * dy + dz * dz + dw * dw;
#pragma unroll
    for (int o = 16; o; o >>= 1) q += __shfl_xor_sync(0xffffffffu, q, o);
    float rs = rsqrtf(q * (1.0f / 128.0f) + 1e-5f);

    float4 g  = *(const float4*)(gamma + lane * 4);
    float4 bt = *(const float4*)(beta + lane * 4);
    float4 o4;
    o4.x = dx * rs * g.x + bt.x;
    o4.y = dy * rs * g.y + bt.y;
    o4.z = dz * rs * g.z + bt.z;
    o4.w = dw * rs * g.w + bt.w;
    *(float4*)(op + lane * 4) = o4;
}

// ---------------- launch --------------------------------------------------------
extern "C" void kernel_launch(void* const* d_in, const int* in_sizes, int n_in,
                              void* d_out, int out_size) {
    const float* user_x = (const float*)d_in[0];
    const float* book_x = (const float*)d_in[1];
    const int*   esrc   = (const int*)d_in[2];
    const int*   edst   = (const int*)d_in[3];
    const float* upw    = (const float*)d_in[4];
    const float* upb    = (const float*)d_in[5];
    const float* bpw    = (const float*)d_in[6];
    const float* bpb    = (const float*)d_in[7];
    const float* Wl     = (const float*)d_in[8];
    const float* bl_    = (const float*)d_in[9];
    const float* Wr     = (const float*)d_in[10];
    const float* ug     = (const float*)d_in[11];
    const float* ube    = (const float*)d_in[12];
    const float* bg     = (const float*)d_in[13];
    const float* bbe    = (const float*)d_in[14];
    float* out = (float*)d_out;

    (void)in_sizes; (void)n_in; (void)out_size;

    cudaFuncSetAttribute(proj_mma, cudaFuncAttributeMaxDynamicSharedMemorySize, SMS_TOT);
    cudaFuncSetAttribute(sage_mma, cudaFuncAttributeMaxDynamicSharedMemorySize, SMS_TOT);

    int* d_offs_u; cudaGetSymbolAddress((void**)&d_offs_u, g_offs_u);
    int* d_offs_b; cudaGetSymbolAddress((void**)&d_offs_b, g_offs_b);
    int* d_deg_u;  cudaGetSymbolAddress((void**)&d_deg_u,  g_deg_u);
    int* d_deg_b;  cudaGetSymbolAddress((void**)&d_deg_b,  g_deg_b);
    int* d_bsum_u; cudaGetSymbolAddress((void**)&d_bsum_u, g_bsum_u);
    int* d_bsum_b; cudaGetSymbolAddress((void**)&d_bsum_b, g_bsum_b);
    int* d_cur_u;  cudaGetSymbolAddress((void**)&d_cur_u,  g_cur_u);
    int* d_cur_b;  cudaGetSymbolAddress((void**)&d_cur_b,  g_cur_b);

    // ---- CSR build ----
    zero_deg_kernel<<<(NU + NB + 255) / 256, 256>>>();
    deg_kernel<<<(NE + 255) / 256, 256>>>(esrc, edst);
    scan_blocks<<<NBLK_U, 1024>>>(d_deg_u, d_offs_u, d_bsum_u, NU);
    scan_blocks<<<NBLK_B, 1024>>>(d_deg_b, d_offs_b, d_bsum_b, NB);
    scan_small<<<1, 256>>>(d_bsum_u, NBLK_U);
    scan_small<<<1, 256>>>(d_bsum_b, NBLK_B);
    scan_add<<<(NU + 255) / 256, 256>>>(d_offs_u, d_bsum_u, d_cur_u, NU, NBLK_U);
    scan_add<<<(NB + 255) / 256, 256>>>(d_offs_b, d_bsum_b, d_cur_b, NB, NBLK_B);
    fill_kernel<<<(NE + 255) / 256, 256>>>(esrc, edst);

    // ---- projections (tensor core, merged) ----
    proj_mma<<<TU + TB, 256, SMS_TOT>>>(user_x, book_x, upw, upb, bpw, bpb);

    int cur = 0;
    const int gblocks = (int)(((size_t)(NU + NB) * 32 + 255) / 256);
    for (int l = 0; l < 3; l++) {
        gather_mean<<<gblocks, 256>>>(cur);
        sage_mma<<<TB + TU, 256, SMS_TOT>>>(cur, Wl + (size_t)l * 128 * 128,
                                            Wr + (size_t)l * 128 * 128,
                                            bl_ + (size_t)l * 128);
        cur ^= 1;
    }

    ln_kernel<<<(int)(((size_t)(NU + NB) * 32 + 255) / 256), 256>>>(
        cur, ug, ube, bg, bbe, out);
}

// round 9
// speedup vs baseline: 1.8689x; 1.3629x over previous
#include <cuda_runtime.h>
#include <cuda_fp16.h>
#include <cstdint>
#include <cstddef>

#define NU 150000
#define NB 75000
#define NE 1500000
#define DU 64
#define DB 128
#define HD 128

#define NBLK_U 147   // ceil(150000/1024)
#define NBLK_B 74    // ceil(75000/1024)
#define TB 586       // ceil(NB/128) tiles
#define TU 1172      // ceil(NU/128) tiles

// ---------------- scratch (fp16 hi-only activations) ---------------------------
__device__ __align__(16) __half g_uh0[(size_t)NU * HD];
__device__ __align__(16) __half g_uh1[(size_t)NU * HD];
__device__ __align__(16) __half g_bh0[(size_t)NB * HD];
__device__ __align__(16) __half g_bh1[(size_t)NB * HD];
__device__ __align__(16) __half g_mh_u[(size_t)NU * HD];   // fp16 neighbor means
__device__ __align__(16) __half g_mh_b[(size_t)NB * HD];
__device__ int g_deg_u[NU];
__device__ int g_deg_b[NB];
__device__ int g_offs_u[NU + 1];
__device__ int g_offs_b[NB + 1];
__device__ int g_bsum_u[NBLK_U + 1];
__device__ int g_bsum_b[NBLK_B + 1];
__device__ int g_cur_u[NU];
__device__ int g_cur_b[NB];
__device__ int g_csr_u[NE];
__device__ int g_csr_b[NE];

__device__ __forceinline__ __half* uh(int i) { return i ? g_uh1 : g_uh0; }
__device__ __forceinline__ __half* bh(int i) { return i ? g_bh1 : g_bh0; }

// ---------------- CSR build ---------------------------------------------------
__global__ void zero_deg_kernel() {
    int i = blockIdx.x * blockDim.x + threadIdx.x;
    if (i < NU) g_deg_u[i] = 0;
    else if (i < NU + NB) g_deg_b[i - NU] = 0;
}

__global__ void deg_kernel(const int* __restrict__ src, const int* __restrict__ dst) {
    int e = blockIdx.x * blockDim.x + threadIdx.x;
    if (e < NE) {
        atomicAdd(&g_deg_u[src[e]], 1);
        atomicAdd(&g_deg_b[dst[e]], 1);
    }
}

__global__ void __launch_bounds__(1024) scan_blocks(
        const int* __restrict__ deg, int* __restrict__ offs,
        int* __restrict__ bsum, int n) {
    __shared__ int wsum[32];
    const int tid = threadIdx.x;
    int i = blockIdx.x * 1024 + tid;
    int v = (i < n) ? deg[i] : 0;
    int x = v;
#pragma unroll
    for (int o = 1; o < 32; o <<= 1) {
        int y = __shfl_up_sync(0xffffffffu, x, o);
        if ((tid & 31) >= o) x += y;
    }
    if ((tid & 31) == 31) wsum[tid >> 5] = x;
    __syncthreads();
    if (tid < 32) {
        int w = wsum[tid];
#pragma unroll
        for (int o = 1; o < 32; o <<= 1) {
            int y = __shfl_up_sync(0xffffffffu, w, o);
            if (tid >= o) w += y;
        }
        wsum[tid] = w;
    }
    __syncthreads();
    int we = (tid >= 32) ? wsum[(tid >> 5) - 1] : 0;
    int incl = x + we;
    if (i < n) offs[i] = incl - v;
    if (tid == 1023) bsum[blockIdx.x] = incl;
}

__global__ void __launch_bounds__(256) scan_small(int* __restrict__ a, int L) {
    __shared__ int wsum[8];
    const int tid = threadIdx.x;
    int v = (tid < L) ? a[tid] : 0;
    int x = v;
#pragma unroll
    for (int o = 1; o < 32; o <<= 1) {
        int y = __shfl_up_sync(0xffffffffu, x, o);
        if ((tid & 31) >= o) x += y;
    }
    if ((tid & 31) == 31) wsum[tid >> 5] = x;
    __syncthreads();
    if (tid == 0) {
        int c = 0;
#pragma unroll
        for (int w = 0; w < 8; w++) { int t = wsum[w]; wsum[w] = c; c += t; }
    }
    __syncthreads();
    int excl = x - v + wsum[tid >> 5];
    if (tid < L) a[tid] = excl;
    if (tid == L) a[L] = excl;
}

__global__ void scan_add(int* __restrict__ offs, const int* __restrict__ bsum,
                         int* __restrict__ cur, int n, int nblk) {
    int i = blockIdx.x * blockDim.x + threadIdx.x;
    if (i < n) {
        int v = offs[i] + bsum[i >> 10];
        offs[i] = v;
        cur[i] = v;
    }
    if (i == 0) offs[n] = bsum[nblk];
}

__global__ void fill_kernel(const int* __restrict__ src, const int* __restrict__ dst) {
    int e = blockIdx.x * blockDim.x + threadIdx.x;
    if (e < NE) {
        int s = src[e], d = dst[e];
        g_csr_u[atomicAdd(&g_cur_u[s], 1)] = d;
        g_csr_b[atomicAdd(&g_cur_b[d], 1)] = s;
    }
}

// ---------------- CSR gather (both directions, 1 warp / dst row) --------------
__global__ void __launch_bounds__(256) gather_mean(int cur) {
    int gw   = (blockIdx.x * blockDim.x + threadIdx.x) >> 5;
    int lane = threadIdx.x & 31;

    int is_user, w;
    if (gw < NB) { is_user = 0; w = gw; }
    else         { is_user = 1; w = gw - NB; if (w >= NU) return; }

    const __half* __restrict__ src = is_user ? bh(cur) : uh(cur);
    __half* __restrict__ out       = is_user ? g_mh_u : g_mh_b;
    const int* __restrict__ offs   = is_user ? g_offs_u : g_offs_b;
    const int* __restrict__ idx    = is_user ? g_csr_u : g_csr_b;

    int s = offs[w], e = offs[w + 1];
    const int c4 = lane * 4;

    float ax = 0.f, ay = 0.f, az = 0.f, aw = 0.f;
    int j = s;
    for (; j + 4 <= e; j += 4) {
        int n0 = idx[j], n1 = idx[j + 1], n2 = idx[j + 2], n3 = idx[j + 3];
        uint2 r0 = *(const uint2*)(src + (size_t)n0 * HD + c4);
        uint2 r1 = *(const uint2*)(src + (size_t)n1 * HD + c4);
        uint2 r2 = *(const uint2*)(src + (size_t)n2 * HD + c4);
        uint2 r3 = *(const uint2*)(src + (size_t)n3 * HD + c4);
#pragma unroll
        for (int q = 0; q < 4; q++) {
            uint2 r = (q == 0) ? r0 : (q == 1) ? r1 : (q == 2) ? r2 : r3;
            float2 f0 = __half22float2(*(__half2*)&r.x);
            float2 f1 = __half22float2(*(__half2*)&r.y);
            ax += f0.x; ay += f0.y; az += f1.x; aw += f1.y;
        }
    }
    for (; j < e; j++) {
        uint2 r = *(const uint2*)(src + (size_t)idx[j] * HD + c4);
        float2 f0 = __half22float2(*(__half2*)&r.x);
        float2 f1 = __half22float2(*(__half2*)&r.y);
        ax += f0.x; ay += f0.y; az += f1.x; aw += f1.y;
    }
    float invd = 1.0f / fmaxf((float)(e - s), 1.0f);
    __half2 m01 = __float22half2_rn(make_float2(ax * invd, ay * invd));
    __half2 m23 = __float22half2_rn(make_float2(az * invd, aw * invd));
    uint2 o; o.x = *(uint32_t*)&m01; o.y = *(uint32_t*)&m23;
    *(uint2*)(out + (size_t)w * HD + c4) = o;
}

// ---------------- shared MMA helper --------------------------------------------
__device__ __forceinline__ void mma16816(float* d, const uint32_t* a,
                                         uint32_t b0, uint32_t b1) {
    asm volatile(
        "mma.sync.aligned.m16n8k16.row.col.f32.f16.f16.f32 "
        "{%0,%1,%2,%3}, {%4,%5,%6,%7}, {%8,%9}, {%0,%1,%2,%3};"
        : "+f"(d[0]), "+f"(d[1]), "+f"(d[2]), "+f"(d[3])
        : "r"(a[0]), "r"(a[1]), "r"(a[2]), "r"(a[3]), "r"(b0), "r"(b1));
}

#define AST 72    // fp16 k-stride in smem (conflict-free fragment loads)

// ---------------- projection GEMM via mma (merged user+book) -------------------
// Inputs fp32 -> exact split-fp16 3-product; output stored fp16 hi only.
#define SMP_BIAS 0
#define SMP_AHI  1024
#define SMP_ALO  (SMP_AHI + 128 * AST * 2)
#define SMP_BHI  (SMP_ALO + 128 * AST * 2)
#define SMP_BLO  (SMP_BHI + 128 * AST * 2)
#define SMP_TOT  (SMP_BLO + 128 * AST * 2)

__global__ void __launch_bounds__(256, 2) proj_mma(
        const float* __restrict__ user_x, const float* __restrict__ book_x,
        const float* __restrict__ upw, const float* __restrict__ upb,
        const float* __restrict__ bpw, const float* __restrict__ bpb) {
    extern __shared__ char smem[];
    const int tid = threadIdx.x;
    const int wid = tid >> 5;
    const int lane = tid & 31;

    const float* A; const float* W; const float* bias;
    __half* Ch;
    int N, K, tile;
    if (blockIdx.x < TU) {
        A = user_x; W = upw; bias = upb; Ch = g_uh0;
        N = NU; K = DU; tile = blockIdx.x;
    } else {
        A = book_x; W = bpw; bias = bpb; Ch = g_bh0;
        N = NB; K = DB; tile = blockIdx.x - TU;
    }
    const int row0 = tile * 128;
    const int nchunks = K >> 6;

    if (tid < 128) *(float*)(smem + SMP_BIAS + tid * 4) = bias[tid];

    const int warp_r = wid >> 1;
    const int warp_c = wid & 1;
    const int gid = lane >> 2;
    const int tig = lane & 3;

    float acc[2][8][4];
#pragma unroll
    for (int t = 0; t < 2; t++)
#pragma unroll
        for (int j = 0; j < 8; j++)
#pragma unroll
            for (int q = 0; q < 4; q++) acc[t][j][q] = 0.f;

    const int a_kq = (tid & 15) * 4;
    const int a_m0 = tid >> 4;
    const int bn = tid & 127;
    const int bk0 = (tid >> 7) * 32;

#pragma unroll 1
    for (int c = 0; c < nchunks; c++) {
        __syncthreads();
        const int kc0 = c * 64;
#pragma unroll
        for (int i = 0; i < 8; i++) {
            int m = a_m0 + i * 16;
            int gr = row0 + m;
            float4 v = make_float4(0.f, 0.f, 0.f, 0.f);
            if (gr < N) v = *(const float4*)(A + (size_t)gr * K + kc0 + a_kq);
            __half2 h01 = __float22half2_rn(make_float2(v.x, v.y));
            __half2 h23 = __float22half2_rn(make_float2(v.z, v.w));
            float2 f01 = __half22float2(h01);
            float2 f23 = __half22float2(h23);
            __half2 l01 = __float22half2_rn(make_float2(v.x - f01.x, v.y - f01.y));
            __half2 l23 = __float22half2_rn(make_float2(v.z - f23.x, v.w - f23.y));
            uint32_t off = (uint32_t)(m * AST + a_kq) * 2;
            *(__half2*)(smem + SMP_AHI + off)     = h01;
            *(__half2*)(smem + SMP_AHI + off + 4) = h23;
            *(__half2*)(smem + SMP_ALO + off)     = l01;
            *(__half2*)(smem + SMP_ALO + off + 4) = l23;
        }
#pragma unroll 8
        for (int j = 0; j < 32; j++) {
            int kk = bk0 + j;
            float w = W[(size_t)(kc0 + kk) * 128 + bn];
            __half h = __float2half_rn(w);
            __half l = __float2half_rn(w - __half2float(h));
            uint32_t off = (uint32_t)(bn * AST + kk) * 2;
            *(__half*)(smem + SMP_BHI + off) = h;
            *(__half*)(smem + SMP_BLO + off) = l;
        }
        __syncthreads();

#pragma unroll
        for (int ks = 0; ks < 4; ks++) {
            const int k0 = ks * 16;
            uint32_t ahr[8], alr[8];
#pragma unroll
            for (int t = 0; t < 2; t++) {
                int r0 = warp_r * 32 + t * 16 + gid;
                uint32_t o0 = (uint32_t)(r0 * AST + k0 + tig * 2) * 2;
                uint32_t o1 = (uint32_t)((r0 + 8) * AST + k0 + tig * 2) * 2;
                ahr[t * 4 + 0] = *(const uint32_t*)(smem + SMP_AHI + o0);
                ahr[t * 4 + 1] = *(const uint32_t*)(smem + SMP_AHI + o1);
                ahr[t * 4 + 2] = *(const uint32_t*)(smem + SMP_AHI + o0 + 16);
                ahr[t * 4 + 3] = *(const uint32_t*)(smem + SMP_AHI + o1 + 16);
                alr[t * 4 + 0] = *(const uint32_t*)(smem + SMP_ALO + o0);
                alr[t * 4 + 1] = *(const uint32_t*)(smem + SMP_ALO + o1);
                alr[t * 4 + 2] = *(const uint32_t*)(smem + SMP_ALO + o0 + 16);
                alr[t * 4 + 3] = *(const uint32_t*)(smem + SMP_ALO + o1 + 16);
            }
#pragma unroll
            for (int j = 0; j < 8; j++) {
                int n = warp_c * 64 + j * 8 + gid;
                uint32_t ob = (uint32_t)(n * AST + k0 + tig * 2) * 2;
                uint32_t bh0 = *(const uint32_t*)(smem + SMP_BHI + ob);
                uint32_t bh1 = *(const uint32_t*)(smem + SMP_BHI + ob + 16);
                uint32_t bl0 = *(const uint32_t*)(smem + SMP_BLO + ob);
                uint32_t bl1 = *(const uint32_t*)(smem + SMP_BLO + ob + 16);
#pragma unroll
                for (int t = 0; t < 2; t++) {
                    mma16816(acc[t][j], ahr + t * 4, bh0, bh1);
                    mma16816(acc[t][j], ahr + t * 4, bl0, bl1);
                    mma16816(acc[t][j], alr + t * 4, bh0, bh1);
                }
            }
        }
    }

    // epilogue: + bias (no relu), fp16 hi store
    const float* bias_s = (const float*)(smem + SMP_BIAS);
#pragma unroll
    for (int t = 0; t < 2; t++) {
        int r_lo = row0 + warp_r * 32 + t * 16 + gid;
        int r_hi = r_lo + 8;
#pragma unroll
        for (int j = 0; j < 8; j++) {
            int col = warp_c * 64 + j * 8 + tig * 2;
            float bx = bias_s[col], by = bias_s[col + 1];
            if (r_lo < N) {
                __half2 h = __float22half2_rn(
                    make_float2(acc[t][j][0] + bx, acc[t][j][1] + by));
                *(__half2*)(Ch + (size_t)r_lo * 128 + col) = h;
            }
            if (r_hi < N) {
                __half2 h = __float22half2_rn(
                    make_float2(acc[t][j][2] + bx, acc[t][j][3] + by));
                *(__half2*)(Ch + (size_t)r_hi * 128 + col) = h;
            }
        }
    }
}

// ---------------- tensor-core SAGE GEMM (hi-only, 1 product everywhere) --------
// out = relu([mean|X] @ [Wl;Wr] + bias), all operands fp16 hi.
#define SMG_BIAS 0
#define SMG_A    1024
#define SMG_B    (SMG_A + 128 * AST * 2)
#define SMG_TOT  (SMG_B + 128 * AST * 2)

__global__ void __launch_bounds__(256, 2) sage_mma(
        int cur,
        const float* __restrict__ Wl, const float* __restrict__ Wr,
        const float* __restrict__ bias) {
    extern __shared__ char smem[];
    const int tid = threadIdx.x;
    const int wid = tid >> 5;
    const int lane = tid & 31;

    int is_user, tile;
    if (blockIdx.x < TB) { is_user = 0; tile = blockIdx.x; }
    else                 { is_user = 1; tile = blockIdx.x - TB; }

    const __half* __restrict__ meanh = is_user ? g_mh_u : g_mh_b;
    const __half* __restrict__ Xh    = is_user ? uh(cur) : bh(cur);
    __half* __restrict__ Oh          = is_user ? uh(cur ^ 1) : bh(cur ^ 1);
    const int N = is_user ? NU : NB;
    const int row0 = tile * 128;

    if (tid < 128) *(float*)(smem + SMG_BIAS + tid * 4) = bias[tid];

    const int warp_r = wid >> 1;
    const int warp_c = wid & 1;
    const int gid = lane >> 2;
    const int tig = lane & 3;

    float acc[2][8][4];
#pragma unroll
    for (int t = 0; t < 2; t++)
#pragma unroll
        for (int j = 0; j < 8; j++)
#pragma unroll
            for (int q = 0; q < 4; q++) acc[t][j][q] = 0.f;

    const int a_kq = (tid & 15) * 4;
    const int a_m0 = tid >> 4;
    const int bn = tid & 127;
    const int bk0 = (tid >> 7) * 32;

#pragma unroll 1
    for (int c = 0; c < 4; c++) {
        __syncthreads();

        const int kg0 = c * 64;
        const bool xpart = (kg0 >= 128);
        const __half* __restrict__ asrc = xpart ? Xh : meanh;
        const int akoff = xpart ? kg0 - 128 : kg0;
#pragma unroll
        for (int i = 0; i < 8; i++) {
            int m = a_m0 + i * 16;
            int gr = row0 + m;
            uint2 vh = make_uint2(0u, 0u);
            if (gr < N) vh = *(const uint2*)(asrc + (size_t)gr * 128 + akoff + a_kq);
            uint32_t off = (uint32_t)(m * AST + a_kq) * 2;
            *(uint2*)(smem + SMG_A + off) = vh;
        }

        const float* __restrict__ wsrc = xpart ? Wr : Wl;
        const int kb = xpart ? kg0 - 128 : kg0;
#pragma unroll 8
        for (int j = 0; j < 32; j++) {
            int kk = bk0 + j;
            __half h = __float2half_rn(wsrc[(size_t)(kb + kk) * 128 + bn]);
            *(__half*)(smem + SMG_B + (uint32_t)(bn * AST + kk) * 2) = h;
        }
        __syncthreads();

#pragma unroll
        for (int ks = 0; ks < 4; ks++) {
            const int k0 = ks * 16;
            uint32_t ahr[8];
#pragma unroll
            for (int t = 0; t < 2; t++) {
                int r0 = warp_r * 32 + t * 16 + gid;
                uint32_t o0 = (uint32_t)(r0 * AST + k0 + tig * 2) * 2;
                uint32_t o1 = (uint32_t)((r0 + 8) * AST + k0 + tig * 2) * 2;
                ahr[t * 4 + 0] = *(const uint32_t*)(smem + SMG_A + o0);
                ahr[t * 4 + 1] = *(const uint32_t*)(smem + SMG_A + o1);
                ahr[t * 4 + 2] = *(const uint32_t*)(smem + SMG_A + o0 + 16);
                ahr[t * 4 + 3] = *(const uint32_t*)(smem + SMG_A + o1 + 16);
            }
#pragma unroll
            for (int j = 0; j < 8; j++) {
                int n = warp_c * 64 + j * 8 + gid;
                uint32_t ob = (uint32_t)(n * AST + k0 + tig * 2) * 2;
                uint32_t bh0 = *(const uint32_t*)(smem + SMG_B + ob);
                uint32_t bh1 = *(const uint32_t*)(smem + SMG_B + ob + 16);
#pragma unroll
                for (int t = 0; t < 2; t++)
                    mma16816(acc[t][j], ahr + t * 4, bh0, bh1);
            }
        }
    }

    // ---- epilogue: bias + relu, fp16 hi store
    const float* bias_s = (const float*)(smem + SMG_BIAS);
#pragma unroll
    for (int t = 0; t < 2; t++) {
        int r_lo = row0 + warp_r * 32 + t * 16 + gid;
        int r_hi = r_lo + 8;
#pragma unroll
        for (int j = 0; j < 8; j++) {
            int col = warp_c * 64 + j * 8 + tig * 2;
            float bx = bias_s[col], by = bias_s[col + 1];
            if (r_lo < N) {
                __half2 h = __float22half2_rn(make_float2(
                    fmaxf(acc[t][j][0] + bx, 0.f), fmaxf(acc[t][j][1] + by, 0.f)));
                *(__half2*)(Oh + (size_t)r_lo * 128 + col) = h;
            }
            if (r_hi < N) {
                __half2 h = __float22half2_rn(make_float2(
                    fmaxf(acc[t][j][2] + bx, 0.f), fmaxf(acc[t][j][3] + by, 0.f)));
                *(__half2*)(Oh + (size_t)r_hi * 128 + col) = h;
            }
        }
    }
}

// ---------------- layernorm (both populations, 1 warp / row) -------------------
__global__ void __launch_bounds__(256) ln_kernel(
        int cur,
        const float* __restrict__ ug, const float* __restrict__ ube,
        const float* __restrict__ bg, const float* __restrict__ bbe,
        float* __restrict__ out) {
    int gw   = (blockIdx.x * blockDim.x + threadIdx.x) >> 5;
    int lane = threadIdx.x & 31;
    if (gw >= NU + NB) return;

    int is_user = (gw < NU);
    int w = is_user ? gw : gw - NU;
    const __half* __restrict__ Xh = is_user ? uh(cur) : bh(cur);
    const float* gamma = is_user ? ug : bg;
    const float* beta  = is_user ? ube : bbe;
    float* op = out + (size_t)gw * 128;

    uint2 vh = *(const uint2*)(Xh + (size_t)w * 128 + lane * 4);
    float2 h0 = __half22float2(*(__half2*)&vh.x);
    float2 h1 = __half22float2(*(__half2*)&vh.y);
    float4 v;
    v.x = h0.x; v.y = h0.y; v.z = h1.x; v.w = h1.y;

    float s = v.x + v.y + v.z + v.w;
#pragma unroll
    for (int o = 16; o; o >>= 1) s += __shfl_xor_sync(0xffffffffu, s, o);
    float mean = s * (1.0f / 128.0f);

    float dx = v.x - mean, dy = v.y - mean, dz = v.z - mean, dw = v.w - mean;
    float q = dx * dx + dy * dy + dz * dz + dw * dw;
#pragma unroll
    for (int o = 16; o; o >>= 1) q += __shfl_xor_sync(0xffffffffu, q, o);
    float rs = rsqrtf(q * (1.0f / 128.0f) + 1e-5f);

    float4 g  = *(const float4*)(gamma + lane * 4);
    float4 bt = *(const float4*)(beta + lane * 4);
    float4 o4;
    o4.x = dx * rs * g.x + bt.x;
    o4.y = dy * rs * g.y + bt.y;
    o4.z = dz * rs * g.z + bt.z;
    o4.w = dw * rs * g.w + bt.w;
    *(float4*)(op + lane * 4) = o4;
}

// ---------------- launch --------------------------------------------------------
extern "C" void kernel_launch(void* const* d_in, const int* in_sizes, int n_in,
                              void* d_out, int out_size) {
    const float* user_x = (const float*)d_in[0];
    const float* book_x = (const float*)d_in[1];
    const int*   esrc   = (const int*)d_in[2];
    const int*   edst   = (const int*)d_in[3];
    const float* upw    = (const float*)d_in[4];
    const float* upb    = (const float*)d_in[5];
    const float* bpw    = (const float*)d_in[6];
    const float* bpb    = (const float*)d_in[7];
    const float* Wl     = (const float*)d_in[8];
    const float* bl_    = (const float*)d_in[9];
    const float* Wr     = (const float*)d_in[10];
    const float* ug     = (const float*)d_in[11];
    const float* ube    = (const float*)d_in[12];
    const float* bg     = (const float*)d_in[13];
    const float* bbe    = (const float*)d_in[14];
    float* out = (float*)d_out;

    (void)in_sizes; (void)n_in; (void)out_size;

    cudaFuncSetAttribute(proj_mma, cudaFuncAttributeMaxDynamicSharedMemorySize, SMP_TOT);
    cudaFuncSetAttribute(sage_mma, cudaFuncAttributeMaxDynamicSharedMemorySize, SMG_TOT);

    int* d_offs_u; cudaGetSymbolAddress((void**)&d_offs_u, g_offs_u);
    int* d_offs_b; cudaGetSymbolAddress((void**)&d_offs_b, g_offs_b);
    int* d_deg_u;  cudaGetSymbolAddress((void**)&d_deg_u,  g_deg_u);
    int* d_deg_b;  cudaGetSymbolAddress((void**)&d_deg_b,  g_deg_b);
    int* d_bsum_u; cudaGetSymbolAddress((void**)&d_bsum_u, g_bsum_u);
    int* d_bsum_b; cudaGetSymbolAddress((void**)&d_bsum_b, g_bsum_b);
    int* d_cur_u;  cudaGetSymbolAddress((void**)&d_cur_u,  g_cur_u);
    int* d_cur_b;  cudaGetSymbolAddress((void**)&d_cur_b,  g_cur_b);

    // ---- CSR build ----
    zero_deg_kernel<<<(NU + NB + 255) / 256, 256>>>();
    deg_kernel<<<(NE + 255) / 256, 256>>>(esrc, edst);
    scan_blocks<<<NBLK_U, 1024>>>(d_deg_u, d_offs_u, d_bsum_u, NU);
    scan_blocks<<<NBLK_B, 1024>>>(d_deg_b, d_offs_b, d_bsum_b, NB);
    scan_small<<<1, 256>>>(d_bsum_u, NBLK_U);
    scan_small<<<1, 256>>>(d_bsum_b, NBLK_B);
    scan_add<<<(NU + 255) / 256, 256>>>(d_offs_u, d_bsum_u, d_cur_u, NU, NBLK_U);
    scan_add<<<(NB + 255) / 256, 256>>>(d_offs_b, d_bsum_b, d_cur_b, NB, NBLK_B);
    fill_kernel<<<(NE + 255) / 256, 256>>>(esrc, edst);

    // ---- projections (tensor core, merged) ----
    proj_mma<<<TU + TB, 256, SMP_TOT>>>(user_x, book_x, upw, upb, bpw, bpb);

    int cur = 0;
    const int gblocks = (int)(((size_t)(NU + NB) * 32 + 255) / 256);
    for (int l = 0; l < 3; l++) {
        gather_mean<<<gblocks, 256>>>(cur);
        sage_mma<<<TB + TU, 256, SMG_TOT>>>(cur, Wl + (size_t)l * 128 * 128,
                                            Wr + (size_t)l * 128 * 128,
                                            bl_ + (size_t)l * 128);
        cur ^= 1;
    }

    ln_kernel<<<(int)(((size_t)(NU + NB) * 32 + 255) / 256), 256>>>(
        cur, ug, ube, bg, bbe, out);
}

// round 11
// speedup vs baseline: 1.8847x; 1.0084x over previous
#include <cuda_runtime.h>
#include <cuda_fp16.h>
#include <cstdint>
#include <cstddef>

#define NU 150000
#define NB 75000
#define NE 1500000
#define DU 64
#define DB 128
#define HD 128

#define NBLK_U 147   // ceil(150000/1024)
#define NBLK_B 74    // ceil(75000/1024)
#define TB 586       // ceil(NB/128) tiles
#define TU 1172      // ceil(NU/128) tiles

// ---------------- scratch (fp16 hi-only activations) ---------------------------
__device__ __align__(16) __half g_uh0[(size_t)NU * HD];
__device__ __align__(16) __half g_uh1[(size_t)NU * HD];
__device__ __align__(16) __half g_bh0[(size_t)NB * HD];
__device__ __align__(16) __half g_bh1[(size_t)NB * HD];
__device__ __align__(16) __half g_mh_u[(size_t)NU * HD];   // fp16 neighbor means
__device__ __align__(16) __half g_mh_b[(size_t)NB * HD];
__device__ __align__(16) __half g_wlt[3 * 128 * 128];      // fp16 n-major Wl
__device__ __align__(16) __half g_wrt[3 * 128 * 128];      // fp16 n-major Wr
__device__ int g_deg_u[NU];
__device__ int g_deg_b[NB];
__device__ int g_offs_u[NU + 1];
__device__ int g_offs_b[NB + 1];
__device__ int g_bsum_u[NBLK_U + 1];
__device__ int g_bsum_b[NBLK_B + 1];
__device__ int g_cur_u[NU];
__device__ int g_cur_b[NB];
__device__ int g_csr_u[NE];
__device__ int g_csr_b[NE];

__device__ __forceinline__ __half* uh(int i) { return i ? g_uh1 : g_uh0; }
__device__ __forceinline__ __half* bh(int i) { return i ? g_bh1 : g_bh0; }

// ---------------- CSR build ---------------------------------------------------
__global__ void deg_kernel(const int* __restrict__ src, const int* __restrict__ dst) {
    int e = blockIdx.x * blockDim.x + threadIdx.x;
    if (e < NE) {
        atomicAdd(&g_deg_u[src[e]], 1);
        atomicAdd(&g_deg_b[dst[e]], 1);
    }
}

__global__ void __launch_bounds__(1024) scan_blocks(
        const int* __restrict__ deg, int* __restrict__ offs,
        int* __restrict__ bsum, int n) {
    __shared__ int wsum[32];
    const int tid = threadIdx.x;
    int i = blockIdx.x * 1024 + tid;
    int v = (i < n) ? deg[i] : 0;
    int x = v;
#pragma unroll
    for (int o = 1; o < 32; o <<= 1) {
        int y = __shfl_up_sync(0xffffffffu, x, o);
        if ((tid & 31) >= o) x += y;
    }
    if ((tid & 31) == 31) wsum[tid >> 5] = x;
    __syncthreads();
    if (tid < 32) {
        int w = wsum[tid];
#pragma unroll
        for (int o = 1; o < 32; o <<= 1) {
            int y = __shfl_up_sync(0xffffffffu, w, o);
            if (tid >= o) w += y;
        }
        wsum[tid] = w;
    }
    __syncthreads();
    int we = (tid >= 32) ? wsum[(tid >> 5) - 1] : 0;
    int incl = x + we;
    if (i < n) offs[i] = incl - v;
    if (tid == 1023) bsum[blockIdx.x] = incl;
}

__global__ void __launch_bounds__(256) scan_small(int* __restrict__ a, int L) {
    __shared__ int wsum[8];
    const int tid = threadIdx.x;
    int v = (tid < L) ? a[tid] : 0;
    int x = v;
#pragma unroll
    for (int o = 1; o < 32; o <<= 1) {
        int y = __shfl_up_sync(0xffffffffu, x, o);
        if ((tid & 31) >= o) x += y;
    }
    if ((tid & 31) == 31) wsum[tid >> 5] = x;
    __syncthreads();
    if (tid == 0) {
        int c = 0;
#pragma unroll
        for (int w = 0; w < 8; w++) { int t = wsum[w]; wsum[w] = c; c += t; }
    }
    __syncthreads();
    int excl = x - v + wsum[tid >> 5];
    if (tid < L) a[tid] = excl;
    if (tid == L) a[L] = excl;
}

__global__ void scan_add(int* __restrict__ offs, const int* __restrict__ bsum,
                         int* __restrict__ cur, int n, int nblk) {
    int i = blockIdx.x * blockDim.x + threadIdx.x;
    if (i < n) {
        int v = offs[i] + bsum[i >> 10];
        offs[i] = v;
        cur[i] = v;
    }
    if (i == 0) offs[n] = bsum[nblk];
}

__global__ void fill_kernel(const int* __restrict__ src, const int* __restrict__ dst) {
    int e = blockIdx.x * blockDim.x + threadIdx.x;
    if (e < NE) {
        int s = src[e], d = dst[e];
        g_csr_u[atomicAdd(&g_cur_u[s], 1)] = d;
        g_csr_b[atomicAdd(&g_cur_b[d], 1)] = s;
    }
}

// ---------------- weight pre-convert: fp32 k-major -> fp16 n-major -------------
__global__ void convert_w(const float* __restrict__ Wl, const float* __restrict__ Wr) {
    int i = blockIdx.x * blockDim.x + threadIdx.x;   // over 3*16384
    if (i < 3 * 16384) {
        int l = i >> 14, r = i & 16383;
        int n = r >> 7, k = r & 127;
        size_t srcoff = ((size_t)l << 14) + k * 128 + n;
        g_wlt[i] = __float2half_rn(Wl[srcoff]);
        g_wrt[i] = __float2half_rn(Wr[srcoff]);
    }
}

// ---------------- CSR gather (both directions, 1 warp / dst row) --------------
__global__ void __launch_bounds__(256) gather_mean(int cur) {
    int gw   = (blockIdx.x * blockDim.x + threadIdx.x) >> 5;
    int lane = threadIdx.x & 31;

    int is_user, w;
    if (gw < NB) { is_user = 0; w = gw; }
    else         { is_user = 1; w = gw - NB; if (w >= NU) return; }

    const __half* __restrict__ src = is_user ? bh(cur) : uh(cur);
    __half* __restrict__ out       = is_user ? g_mh_u : g_mh_b;
    const int* __restrict__ offs   = is_user ? g_offs_u : g_offs_b;
    const int* __restrict__ idx    = is_user ? g_csr_u : g_csr_b;

    int s = offs[w], e = offs[w + 1];
    const int c4 = lane * 4;

    float ax = 0.f, ay = 0.f, az = 0.f, aw = 0.f;
    int j = s;
    for (; j + 4 <= e; j += 4) {
        int n0 = idx[j], n1 = idx[j + 1], n2 = idx[j + 2], n3 = idx[j + 3];
        uint2 r0 = *(const uint2*)(src + (size_t)n0 * HD + c4);
        uint2 r1 = *(const uint2*)(src + (size_t)n1 * HD + c4);
        uint2 r2 = *(const uint2*)(src + (size_t)n2 * HD + c4);
        uint2 r3 = *(const uint2*)(src + (size_t)n3 * HD + c4);
#pragma unroll
        for (int q = 0; q < 4; q++) {
            uint2 r = (q == 0) ? r0 : (q == 1) ? r1 : (q == 2) ? r2 : r3;
            float2 f0 = __half22float2(*(__half2*)&r.x);
            float2 f1 = __half22float2(*(__half2*)&r.y);
            ax += f0.x; ay += f0.y; az += f1.x; aw += f1.y;
        }
    }
    for (; j < e; j++) {
        uint2 r = *(const uint2*)(src + (size_t)idx[j] * HD + c4);
        float2 f0 = __half22float2(*(__half2*)&r.x);
        float2 f1 = __half22float2(*(__half2*)&r.y);
        ax += f0.x; ay += f0.y; az += f1.x; aw += f1.y;
    }
    float invd = 1.0f / fmaxf((float)(e - s), 1.0f);
    __half2 m01 = __float22half2_rn(make_float2(ax * invd, ay * invd));
    __half2 m23 = __float22half2_rn(make_float2(az * invd, aw * invd));
    uint2 o; o.x = *(uint32_t*)&m01; o.y = *(uint32_t*)&m23;
    *(uint2*)(out + (size_t)w * HD + c4) = o;
}

// ---------------- shared MMA helper --------------------------------------------
__device__ __forceinline__ void mma16816(float* d, const uint32_t* a,
                                         uint32_t b0, uint32_t b1) {
    asm volatile(
        "mma.sync.aligned.m16n8k16.row.col.f32.f16.f16.f32 "
        "{%0,%1,%2,%3}, {%4,%5,%6,%7}, {%8,%9}, {%0,%1,%2,%3};"
        : "+f"(d[0]), "+f"(d[1]), "+f"(d[2]), "+f"(d[3])
        : "r"(a[0]), "r"(a[1]), "r"(a[2]), "r"(a[3]), "r"(b0), "r"(b1));
}

#define AST 72    // fp16 k-stride in smem (conflict-free fragment loads)

// ---------------- projection GEMM via mma (merged user+book) -------------------
// Inputs fp32 -> exact split-fp16 3-product; output stored fp16 hi only.
#define SMP_BIAS 0
#define SMP_AHI  1024
#define SMP_ALO  (SMP_AHI + 128 * AST * 2)
#define SMP_BHI  (SMP_ALO + 128 * AST * 2)
#define SMP_BLO  (SMP_BHI + 128 * AST * 2)
#define SMP_TOT  (SMP_BLO + 128 * AST * 2)

__global__ void __launch_bounds__(256, 2) proj_mma(
        const float* __restrict__ user_x, const float* __restrict__ book_x,
        const float* __restrict__ upw, const float* __restrict__ upb,
        const float* __restrict__ bpw, const float* __restrict__ bpb) {
    extern __shared__ char smem[];
    const int tid = threadIdx.x;
    const int wid = tid >> 5;
    const int lane = tid & 31;

    const float* A; const float* W; const float* bias;
    __half* Ch;
    int N, K, tile;
    if (blockIdx.x < TU) {
        A = user_x; W = upw; bias = upb; Ch = g_uh0;
        N = NU; K = DU; tile = blockIdx.x;
    } else {
        A = book_x; W = bpw; bias = bpb; Ch = g_bh0;
        N = NB; K = DB; tile = blockIdx.x - TU;
    }
    const int row0 = tile * 128;
    const int nchunks = K >> 6;

    if (tid < 128) *(float*)(smem + SMP_BIAS + tid * 4) = bias[tid];

    const int warp_r = wid >> 1;
    const int warp_c = wid & 1;
    const int gid = lane >> 2;
    const int tig = lane & 3;

    float acc[2][8][4];
#pragma unroll
    for (int t = 0; t < 2; t++)
#pragma unroll
        for (int j = 0; j < 8; j++)
#pragma unroll
            for (int q = 0; q < 4; q++) acc[t][j][q] = 0.f;

    const int a_kq = (tid & 15) * 4;
    const int a_m0 = tid >> 4;
    const int bn = tid & 127;
    const int bk0 = (tid >> 7) * 32;

#pragma unroll 1
    for (int c = 0; c < nchunks; c++) {
        __syncthreads();
        const int kc0 = c * 64;
#pragma unroll
        for (int i = 0; i < 8; i++) {
            int m = a_m0 + i * 16;
            int gr = row0 + m;
            float4 v = make_float4(0.f, 0.f, 0.f, 0.f);
            if (gr < N) v = *(const float4*)(A + (size_t)gr * K + kc0 + a_kq);
            __half2 h01 = __float22half2_rn(make_float2(v.x, v.y));
            __half2 h23 = __float22half2_rn(make_float2(v.z, v.w));
            float2 f01 = __half22float2(h01);
            float2 f23 = __half22float2(h23);
            __half2 l01 = __float22half2_rn(make_float2(v.x - f01.x, v.y - f01.y));
            __half2 l23 = __float22half2_rn(make_float2(v.z - f23.x, v.w - f23.y));
            uint32_t off = (uint32_t)(m * AST + a_kq) * 2;
            *(__half2*)(smem + SMP_AHI + off)     = h01;
            *(__half2*)(smem + SMP_AHI + off + 4) = h23;
            *(__half2*)(smem + SMP_ALO + off)     = l01;
            *(__half2*)(smem + SMP_ALO + off + 4) = l23;
        }
#pragma unroll 8
        for (int j = 0; j < 32; j++) {
            int kk = bk0 + j;
            float w = W[(size_t)(kc0 + kk) * 128 + bn];
            __half h = __float2half_rn(w);
            __half l = __float2half_rn(w - __half2float(h));
            uint32_t off = (uint32_t)(bn * AST + kk) * 2;
            *(__half*)(smem + SMP_BHI + off) = h;
            *(__half*)(smem + SMP_BLO + off) = l;
        }
        __syncthreads();

#pragma unroll
        for (int ks = 0; ks < 4; ks++) {
            const int k0 = ks * 16;
            uint32_t ahr[8], alr[8];
#pragma unroll
            for (int t = 0; t < 2; t++) {
                int r0 = warp_r * 32 + t * 16 + gid;
                uint32_t o0 = (uint32_t)(r0 * AST + k0 + tig * 2) * 2;
                uint32_t o1 = (uint32_t)((r0 + 8) * AST + k0 + tig * 2) * 2;
                ahr[t * 4 + 0] = *(const uint32_t*)(smem + SMP_AHI + o0);
                ahr[t * 4 + 1] = *(const uint32_t*)(smem + SMP_AHI + o1);
                ahr[t * 4 + 2] = *(const uint32_t*)(smem + SMP_AHI + o0 + 16);
                ahr[t * 4 + 3] = *(const uint32_t*)(smem + SMP_AHI + o1 + 16);
                alr[t * 4 + 0] = *(const uint32_t*)(smem + SMP_ALO + o0);
                alr[t * 4 + 1] = *(const uint32_t*)(smem + SMP_ALO + o1);
                alr[t * 4 + 2] = *(const uint32_t*)(smem + SMP_ALO + o0 + 16);
                alr[t * 4 + 3] = *(const uint32_t*)(smem + SMP_ALO + o1 + 16);
            }
#pragma unroll
            for (int j = 0; j < 8; j++) {
                int n = warp_c * 64 + j * 8 + gid;
                uint32_t ob = (uint32_t)(n * AST + k0 + tig * 2) * 2;
                uint32_t bh0 = *(const uint32_t*)(smem + SMP_BHI + ob);
                uint32_t bh1 = *(const uint32_t*)(smem + SMP_BHI + ob + 16);
                uint32_t bl0 = *(const uint32_t*)(smem + SMP_BLO + ob);
                uint32_t bl1 = *(const uint32_t*)(smem + SMP_BLO + ob + 16);
#pragma unroll
                for (int t = 0; t < 2; t++) {
                    mma16816(acc[t][j], ahr + t * 4, bh0, bh1);
                    mma16816(acc[t][j], ahr + t * 4, bl0, bl1);
                    mma16816(acc[t][j], alr + t * 4, bh0, bh1);
                }
            }
        }
    }

    // epilogue: + bias (no relu), fp16 hi store
    const float* bias_s = (const float*)(smem + SMP_BIAS);
#pragma unroll
    for (int t = 0; t < 2; t++) {
        int r_lo = row0 + warp_r * 32 + t * 16 + gid;
        int r_hi = r_lo + 8;
#pragma unroll
        for (int j = 0; j < 8; j++) {
            int col = warp_c * 64 + j * 8 + tig * 2;
            float bx = bias_s[col], by = bias_s[col + 1];
            if (r_lo < N) {
                __half2 h = __float22half2_rn(
                    make_float2(acc[t][j][0] + bx, acc[t][j][1] + by));
                *(__half2*)(Ch + (size_t)r_lo * 128 + col) = h;
            }
            if (r_hi < N) {
                __half2 h = __float22half2_rn(
                    make_float2(acc[t][j][2] + bx, acc[t][j][3] + by));
                *(__half2*)(Ch + (size_t)r_hi * 128 + col) = h;
            }
        }
    }
}

// ---------------- tensor-core SAGE GEMM (hi-only; pre-converted fp16 W) --------
// out = relu([mean|X] @ [Wl;Wr] + bias), all operands fp16.
#define SMG_BIAS 0
#define SMG_A    1024
#define SMG_B    (SMG_A + 128 * AST * 2)
#define SMG_TOT  (SMG_B + 128 * AST * 2)

__global__ void __launch_bounds__(256, 2) sage_mma(
        int cur,
        const __half* __restrict__ Wlt, const __half* __restrict__ Wrt,
        const float* __restrict__ bias) {
    extern __shared__ char smem[];
    const int tid = threadIdx.x;
    const int wid = tid >> 5;
    const int lane = tid & 31;

    int is_user, tile;
    if (blockIdx.x < TB) { is_user = 0; tile = blockIdx.x; }
    else                 { is_user = 1; tile = blockIdx.x - TB; }

    const __half* __restrict__ meanh = is_user ? g_mh_u : g_mh_b;
    const __half* __restrict__ Xh    = is_user ? uh(cur) : bh(cur);
    __half* __restrict__ Oh          = is_user ? uh(cur ^ 1) : bh(cur ^ 1);
    const int N = is_user ? NU : NB;
    const int row0 = tile * 128;

    if (tid < 128) *(float*)(smem + SMG_BIAS + tid * 4) = bias[tid];

    const int warp_r = wid >> 1;
    const int warp_c = wid & 1;
    const int gid = lane >> 2;
    const int tig = lane & 3;

    float acc[2][8][4];
#pragma unroll
    for (int t = 0; t < 2; t++)
#pragma unroll
        for (int j = 0; j < 8; j++)
#pragma unroll
            for (int q = 0; q < 4; q++) acc[t][j][q] = 0.f;

    const int a_kq = (tid & 15) * 4;
    const int a_m0 = tid >> 4;
    const int bn = tid & 127;
    const int bk0 = (tid >> 7) * 32;

#pragma unroll 1
    for (int c = 0; c < 4; c++) {
        __syncthreads();

        const int kg0 = c * 64;
        const bool xpart = (kg0 >= 128);
        const __half* __restrict__ asrc = xpart ? Xh : meanh;
        const int akoff = xpart ? kg0 - 128 : kg0;
#pragma unroll
        for (int i = 0; i < 8; i++) {
            int m = a_m0 + i * 16;
            int gr = row0 + m;
            uint2 vh = make_uint2(0u, 0u);
            if (gr < N) vh = *(const uint2*)(asrc + (size_t)gr * 128 + akoff + a_kq);
            uint32_t off = (uint32_t)(m * AST + a_kq) * 2;
            *(uint2*)(smem + SMG_A + off) = vh;
        }

        // B staging: fp16 n-major, vectorized copy — 4 x uint4 = 32 halfs (full k-range)
        const __half* __restrict__ wsrc = (xpart ? Wrt : Wlt) + (size_t)bn * 128
                                          + (xpart ? kg0 - 128 : kg0) + bk0;
#pragma unroll
        for (int j = 0; j < 4; j++) {
            uint4 v = *(const uint4*)(wsrc + j * 8);
            *(uint4*)(smem + SMG_B + (uint32_t)(bn * AST + bk0 + j * 8) * 2) = v;
        }
        __syncthreads();

#pragma unroll
        for (int ks = 0; ks < 4; ks++) {
            const int k0 = ks * 16;
            uint32_t ahr[8];
#pragma unroll
            for (int t = 0; t < 2; t++) {
                int r0 = warp_r * 32 + t * 16 + gid;
                uint32_t o0 = (uint32_t)(r0 * AST + k0 + tig * 2) * 2;
                uint32_t o1 = (uint32_t)((r0 + 8) * AST + k0 + tig * 2) * 2;
                ahr[t * 4 + 0] = *(const uint32_t*)(smem + SMG_A + o0);
                ahr[t * 4 + 1] = *(const uint32_t*)(smem + SMG_A + o1);
                ahr[t * 4 + 2] = *(const uint32_t*)(smem + SMG_A + o0 + 16);
                ahr[t * 4 + 3] = *(const uint32_t*)(smem + SMG_A + o1 + 16);
            }
#pragma unroll
            for (int j = 0; j < 8; j++) {
                int n = warp_c * 64 + j * 8 + gid;
                uint32_t ob = (uint32_t)(n * AST + k0 + tig * 2) * 2;
                uint32_t bh0 = *(const uint32_t*)(smem + SMG_B + ob);
                uint32_t bh1 = *(const uint32_t*)(smem + SMG_B + ob + 16);
#pragma unroll
                for (int t = 0; t < 2; t++)
                    mma16816(acc[t][j], ahr + t * 4, bh0, bh1);
            }
        }
    }

    // ---- epilogue: bias + relu, fp16 hi store
    const float* bias_s = (const float*)(smem + SMG_BIAS);
#pragma unroll
    for (int t = 0; t < 2; t++) {
        int r_lo = row0 + warp_r * 32 + t * 16 + gid;
        int r_hi = r_lo + 8;
#pragma unroll
        for (int j = 0; j < 8; j++) {
            int col = warp_c * 64 + j * 8 + tig * 2;
            float bx = bias_s[col], by = bias_s[col + 1];
            if (r_lo < N) {
                __half2 h = __float22half2_rn(make_float2(
                    fmaxf(acc[t][j][0] + bx, 0.f), fmaxf(acc[t][j][1] + by, 0.f)));
                *(__half2*)(Oh + (size_t)r_lo * 128 + col) = h;
            }
            if (r_hi < N) {
                __half2 h = __float22half2_rn(make_float2(
                    fmaxf(acc[t][j][2] + bx, 0.f), fmaxf(acc[t][j][3] + by, 0.f)));
                *(__half2*)(Oh + (size_t)r_hi * 128 + col) = h;
            }
        }
    }
}

// ---------------- layernorm (both populations, 1 warp / row) -------------------
__global__ void __launch_bounds__(256) ln_kernel(
        int cur,
        const float* __restrict__ ug, const float* __restrict__ ube,
        const float* __restrict__ bg, const float* __restrict__ bbe,
        float* __restrict__ out) {
    int gw   = (blockIdx.x * blockDim.x + threadIdx.x) >> 5;
    int lane = threadIdx.x & 31;
    if (gw >= NU + NB) return;

    int is_user = (gw < NU);
    int w = is_user ? gw : gw - NU;
    const __half* __restrict__ Xh = is_user ? uh(cur) : bh(cur);
    const float* gamma = is_user ? ug : bg;
    const float* beta  = is_user ? ube : bbe;
    float* op = out + (size_t)gw * 128;

    uint2 vh = *(const uint2*)(Xh + (size_t)w * 128 + lane * 4);
    float2 h0 = __half22float2(*(__half2*)&vh.x);
    float2 h1 = __half22float2(*(__half2*)&vh.y);
    float4 v;
    v.x = h0.x; v.y = h0.y; v.z = h1.x; v.w = h1.y;

    float s = v.x + v.y + v.z + v.w;
#pragma unroll
    for (int o = 16; o; o >>= 1) s += __shfl_xor_sync(0xffffffffu, s, o);
    float mean = s * (1.0f / 128.0f);

    float dx = v.x - mean, dy = v.y - mean, dz = v.z - mean, dw = v.w - mean;
    float q = dx * dx + dy * dy + dz * dz + dw * dw;
#pragma unroll
    for (int o = 16; o; o >>= 1) q += __shfl_xor_sync(0xffffffffu, q, o);
    float rs = rsqrtf(q * (1.0f / 128.0f) + 1e-5f);

    float4 g  = *(const float4*)(gamma + lane * 4);
    float4 bt = *(const float4*)(beta + lane * 4);
    float4 o4;
    o4.x = dx * rs * g.x + bt.x;
    o4.y = dy * rs * g.y + bt.y;
    o4.z = dz * rs * g.z + bt.z;
    o4.w = dw * rs * g.w + bt.w;
    *(float4*)(op + lane * 4) = o4;
}

// ---------------- launch --------------------------------------------------------
extern "C" void kernel_launch(void* const* d_in, const int* in_sizes, int n_in,
                              void* d_out, int out_size) {
    const float* user_x = (const float*)d_in[0];
    const float* book_x = (const float*)d_in[1];
    const int*   esrc   = (const int*)d_in[2];
    const int*   edst   = (const int*)d_in[3];
    const float* upw    = (const float*)d_in[4];
    const float* upb    = (const float*)d_in[5];
    const float* bpw    = (const float*)d_in[6];
    const float* bpb    = (const float*)d_in[7];
    const float* Wl     = (const float*)d_in[8];
    const float* bl_    = (const float*)d_in[9];
    const float* Wr     = (const float*)d_in[10];
    const float* ug     = (const float*)d_in[11];
    const float* ube    = (const float*)d_in[12];
    const float* bg     = (const float*)d_in[13];
    const float* bbe    = (const float*)d_in[14];
    float* out = (float*)d_out;

    (void)in_sizes; (void)n_in; (void)out_size;

    cudaFuncSetAttribute(proj_mma, cudaFuncAttributeMaxDynamicSharedMemorySize, SMP_TOT);
    cudaFuncSetAttribute(sage_mma, cudaFuncAttributeMaxDynamicSharedMemorySize, SMG_TOT);

    int* d_offs_u; cudaGetSymbolAddress((void**)&d_offs_u, g_offs_u);
    int* d_offs_b; cudaGetSymbolAddress((void**)&d_offs_b, g_offs_b);
    int* d_deg_u;  cudaGetSymbolAddress((void**)&d_deg_u,  g_deg_u);
    int* d_deg_b;  cudaGetSymbolAddress((void**)&d_deg_b,  g_deg_b);
    int* d_bsum_u; cudaGetSymbolAddress((void**)&d_bsum_u, g_bsum_u);
    int* d_bsum_b; cudaGetSymbolAddress((void**)&d_bsum_b, g_bsum_b);
    int* d_cur_u;  cudaGetSymbolAddress((void**)&d_cur_u,  g_cur_u);
    int* d_cur_b;  cudaGetSymbolAddress((void**)&d_cur_b,  g_cur_b);
    __half* d_wlt; cudaGetSymbolAddress((void**)&d_wlt, g_wlt);
    __half* d_wrt; cudaGetSymbolAddress((void**)&d_wrt, g_wrt);

    // ---- CSR build ----
    cudaMemsetAsync(d_deg_u, 0, NU * sizeof(int));
    cudaMemsetAsync(d_deg_b, 0, NB * sizeof(int));
    deg_kernel<<<(NE + 255) / 256, 256>>>(esrc, edst);
    scan_blocks<<<NBLK_U, 1024>>>(d_deg_u, d_offs_u, d_bsum_u, NU);
    scan_blocks<<<NBLK_B, 1024>>>(d_deg_b, d_offs_b, d_bsum_b, NB);
    scan_small<<<1, 256>>>(d_bsum_u, NBLK_U);
    scan_small<<<1, 256>>>(d_bsum_b, NBLK_B);
    scan_add<<<(NU + 255) / 256, 256>>>(d_offs_u, d_bsum_u, d_cur_u, NU, NBLK_U);
    scan_add<<<(NB + 255) / 256, 256>>>(d_offs_b, d_bsum_b, d_cur_b, NB, NBLK_B);
    fill_kernel<<<(NE + 255) / 256, 256>>>(esrc, edst);

    // ---- weight pre-convert + projections ----
    convert_w<<<(3 * 16384 + 255) / 256, 256>>>(Wl, Wr);
    proj_mma<<<TU + TB, 256, SMP_TOT>>>(user_x, book_x, upw, upb, bpw, bpb);

    int cur = 0;
    const int gblocks = (int)(((size_t)(NU + NB) * 32 + 255) / 256);
    for (int l = 0; l < 3; l++) {
        gather_mean<<<gblocks, 256>>>(cur);
        sage_mma<<<TB + TU, 256, SMG_TOT>>>(cur, d_wlt + (size_t)l * 16384,
                                            d_wrt + (size_t)l * 16384,
                                            bl_ + (size_t)l * 128);
        cur ^= 1;
    }

    ln_kernel<<<(int)(((size_t)(NU + NB) * 32 + 255) / 256), 256>>>(
        cur, ug, ube, bg, bbe, out);
}

// round 12
// speedup vs baseline: 1.9161x; 1.0166x over previous
#include <cuda_runtime.h>
#include <cuda_fp16.h>
#include <cstdint>
#include <cstddef>

#define NU 150000
#define NB 75000
#define NE 1500000
#define DU 64
#define DB 128
#define HD 128

#define NBLK_U 147   // ceil(150000/1024)
#define NBLK_B 74    // ceil(75000/1024)
#define TB 586       // ceil(NB/128) tiles
#define TU 1172      // ceil(NU/128) tiles

// ---------------- scratch (fp16 hi-only activations) ---------------------------
__device__ __align__(16) __half g_uh0[(size_t)NU * HD];
__device__ __align__(16) __half g_uh1[(size_t)NU * HD];
__device__ __align__(16) __half g_bh0[(size_t)NB * HD];
__device__ __align__(16) __half g_bh1[(size_t)NB * HD];
__device__ __align__(16) __half g_mu0[(size_t)NU * HD];   // means, parity buffers
__device__ __align__(16) __half g_mu1[(size_t)NU * HD];
__device__ __align__(16) __half g_mb0[(size_t)NB * HD];
__device__ __align__(16) __half g_mb1[(size_t)NB * HD];
__device__ __align__(16) __half g_wlt[3 * 128 * 128];      // fp16 n-major Wl
__device__ __align__(16) __half g_wrt[3 * 128 * 128];      // fp16 n-major Wr
__device__ int g_deg_u[NU];
__device__ int g_deg_b[NB];
__device__ int g_offs_u[NU + 1];
__device__ int g_offs_b[NB + 1];
__device__ int g_bsum_u[NBLK_U + 1];
__device__ int g_bsum_b[NBLK_B + 1];
__device__ int g_cur_u[NU];
__device__ int g_cur_b[NB];
__device__ int g_csr_u[NE];
__device__ int g_csr_b[NE];

__device__ __forceinline__ __half* uh(int i) { return i ? g_uh1 : g_uh0; }
__device__ __forceinline__ __half* bh(int i) { return i ? g_bh1 : g_bh0; }
__device__ __forceinline__ __half* mu(int i) { return i ? g_mu1 : g_mu0; }
__device__ __forceinline__ __half* mb(int i) { return i ? g_mb1 : g_mb0; }

// ---------------- CSR build ---------------------------------------------------
__global__ void deg_kernel(const int* __restrict__ src, const int* __restrict__ dst) {
    int e = blockIdx.x * blockDim.x + threadIdx.x;
    if (e < NE) {
        atomicAdd(&g_deg_u[src[e]], 1);
        atomicAdd(&g_deg_b[dst[e]], 1);
    }
}

__global__ void __launch_bounds__(1024) scan_blocks(
        const int* __restrict__ deg, int* __restrict__ offs,
        int* __restrict__ bsum, int n) {
    __shared__ int wsum[32];
    const int tid = threadIdx.x;
    int i = blockIdx.x * 1024 + tid;
    int v = (i < n) ? deg[i] : 0;
    int x = v;
#pragma unroll
    for (int o = 1; o < 32; o <<= 1) {
        int y = __shfl_up_sync(0xffffffffu, x, o);
        if ((tid & 31) >= o) x += y;
    }
    if ((tid & 31) == 31) wsum[tid >> 5] = x;
    __syncthreads();
    if (tid < 32) {
        int w = wsum[tid];
#pragma unroll
        for (int o = 1; o < 32; o <<= 1) {
            int y = __shfl_up_sync(0xffffffffu, w, o);
            if (tid >= o) w += y;
        }
        wsum[tid] = w;
    }
    __syncthreads();
    int we = (tid >= 32) ? wsum[(tid >> 5) - 1] : 0;
    int incl = x + we;
    if (i < n) offs[i] = incl - v;
    if (tid == 1023) bsum[blockIdx.x] = incl;
}

__global__ void __launch_bounds__(256) scan_small(int* __restrict__ a, int L) {
    __shared__ int wsum[8];
    const int tid = threadIdx.x;
    int v = (tid < L) ? a[tid] : 0;
    int x = v;
#pragma unroll
    for (int o = 1; o < 32; o <<= 1) {
        int y = __shfl_up_sync(0xffffffffu, x, o);
        if ((tid & 31) >= o) x += y;
    }
    if ((tid & 31) == 31) wsum[tid >> 5] = x;
    __syncthreads();
    if (tid == 0) {
        int c = 0;
#pragma unroll
        for (int w = 0; w < 8; w++) { int t = wsum[w]; wsum[w] = c; c += t; }
    }
    __syncthreads();
    int excl = x - v + wsum[tid >> 5];
    if (tid < L) a[tid] = excl;
    if (tid == L) a[L] = excl;
}

__global__ void scan_add(int* __restrict__ offs, const int* __restrict__ bsum,
                         int* __restrict__ cur, int n, int nblk) {
    int i = blockIdx.x * blockDim.x + threadIdx.x;
    if (i < n) {
        int v = offs[i] + bsum[i >> 10];
        offs[i] = v;
        cur[i] = v;
    }
    if (i == 0) offs[n] = bsum[nblk];
}

__global__ void fill_kernel(const int* __restrict__ src, const int* __restrict__ dst) {
    int e = blockIdx.x * blockDim.x + threadIdx.x;
    if (e < NE) {
        int s = src[e], d = dst[e];
        g_csr_u[atomicAdd(&g_cur_u[s], 1)] = d;
        g_csr_b[atomicAdd(&g_cur_b[d], 1)] = s;
    }
}

// ---------------- weight pre-convert: fp32 k-major -> fp16 n-major -------------
__global__ void convert_w(const float* __restrict__ Wl, const float* __restrict__ Wr) {
    int i = blockIdx.x * blockDim.x + threadIdx.x;   // over 3*16384
    if (i < 3 * 16384) {
        int l = i >> 14, r = i & 16383;
        int n = r >> 7, k = r & 127;
        size_t srcoff = ((size_t)l << 14) + k * 128 + n;
        g_wlt[i] = __float2half_rn(Wl[srcoff]);
        g_wrt[i] = __float2half_rn(Wr[srcoff]);
    }
}

// ---------------- CSR gather (single direction, 1 warp / dst row) --------------
__global__ void __launch_bounds__(256) gather_mean(int is_user, int cur, int mbuf) {
    int w    = (blockIdx.x * blockDim.x + threadIdx.x) >> 5;
    int lane = threadIdx.x & 31;
    const int N = is_user ? NU : NB;
    if (w >= N) return;

    const __half* __restrict__ src = is_user ? bh(cur) : uh(cur);
    __half* __restrict__ out       = is_user ? mu(mbuf) : mb(mbuf);
    const int* __restrict__ offs   = is_user ? g_offs_u : g_offs_b;
    const int* __restrict__ idx    = is_user ? g_csr_u : g_csr_b;

    int s = offs[w], e = offs[w + 1];
    const int c4 = lane * 4;

    float ax = 0.f, ay = 0.f, az = 0.f, aw = 0.f;
    int j = s;
    for (; j + 4 <= e; j += 4) {
        int n0 = idx[j], n1 = idx[j + 1], n2 = idx[j + 2], n3 = idx[j + 3];
        uint2 r0 = *(const uint2*)(src + (size_t)n0 * HD + c4);
        uint2 r1 = *(const uint2*)(src + (size_t)n1 * HD + c4);
        uint2 r2 = *(const uint2*)(src + (size_t)n2 * HD + c4);
        uint2 r3 = *(const uint2*)(src + (size_t)n3 * HD + c4);
#pragma unroll
        for (int q = 0; q < 4; q++) {
            uint2 r = (q == 0) ? r0 : (q == 1) ? r1 : (q == 2) ? r2 : r3;
            float2 f0 = __half22float2(*(__half2*)&r.x);
            float2 f1 = __half22float2(*(__half2*)&r.y);
            ax += f0.x; ay += f0.y; az += f1.x; aw += f1.y;
        }
    }
    for (; j < e; j++) {
        uint2 r = *(const uint2*)(src + (size_t)idx[j] * HD + c4);
        float2 f0 = __half22float2(*(__half2*)&r.x);
        float2 f1 = __half22float2(*(__half2*)&r.y);
        ax += f0.x; ay += f0.y; az += f1.x; aw += f1.y;
    }
    float invd = 1.0f / fmaxf((float)(e - s), 1.0f);
    __half2 m01 = __float22half2_rn(make_float2(ax * invd, ay * invd));
    __half2 m23 = __float22half2_rn(make_float2(az * invd, aw * invd));
    uint2 o; o.x = *(uint32_t*)&m01; o.y = *(uint32_t*)&m23;
    *(uint2*)(out + (size_t)w * HD + c4) = o;
}

// ---------------- shared MMA helper --------------------------------------------
__device__ __forceinline__ void mma16816(float* d, const uint32_t* a,
                                         uint32_t b0, uint32_t b1) {
    asm volatile(
        "mma.sync.aligned.m16n8k16.row.col.f32.f16.f16.f32 "
        "{%0,%1,%2,%3}, {%4,%5,%6,%7}, {%8,%9}, {%0,%1,%2,%3};"
        : "+f"(d[0]), "+f"(d[1]), "+f"(d[2]), "+f"(d[3])
        : "r"(a[0]), "r"(a[1]), "r"(a[2]), "r"(a[3]), "r"(b0), "r"(b1));
}

#define AST 72    // fp16 k-stride in smem (conflict-free fragment loads)

// ---------------- projection GEMM via mma (merged user+book) -------------------
#define SMP_BIAS 0
#define SMP_AHI  1024
#define SMP_ALO  (SMP_AHI + 128 * AST * 2)
#define SMP_BHI  (SMP_ALO + 128 * AST * 2)
#define SMP_BLO  (SMP_BHI + 128 * AST * 2)
#define SMP_TOT  (SMP_BLO + 128 * AST * 2)

__global__ void __launch_bounds__(256, 2) proj_mma(
        const float* __restrict__ user_x, const float* __restrict__ book_x,
        const float* __restrict__ upw, const float* __restrict__ upb,
        const float* __restrict__ bpw, const float* __restrict__ bpb) {
    extern __shared__ char smem[];
    const int tid = threadIdx.x;
    const int wid = tid >> 5;
    const int lane = tid & 31;

    const float* A; const float* W; const float* bias;
    __half* Ch;
    int N, K, tile;
    if (blockIdx.x < TU) {
        A = user_x; W = upw; bias = upb; Ch = g_uh0;
        N = NU; K = DU; tile = blockIdx.x;
    } else {
        A = book_x; W = bpw; bias = bpb; Ch = g_bh0;
        N = NB; K = DB; tile = blockIdx.x - TU;
    }
    const int row0 = tile * 128;
    const int nchunks = K >> 6;

    if (tid < 128) *(float*)(smem + SMP_BIAS + tid * 4) = bias[tid];

    const int warp_r = wid >> 1;
    const int warp_c = wid & 1;
    const int gid = lane >> 2;
    const int tig = lane & 3;

    float acc[2][8][4];
#pragma unroll
    for (int t = 0; t < 2; t++)
#pragma unroll
        for (int j = 0; j < 8; j++)
#pragma unroll
            for (int q = 0; q < 4; q++) acc[t][j][q] = 0.f;

    const int a_kq = (tid & 15) * 4;
    const int a_m0 = tid >> 4;
    const int bn = tid & 127;
    const int bk0 = (tid >> 7) * 32;

#pragma unroll 1
    for (int c = 0; c < nchunks; c++) {
        __syncthreads();
        const int kc0 = c * 64;
#pragma unroll
        for (int i = 0; i < 8; i++) {
            int m = a_m0 + i * 16;
            int gr = row0 + m;
            float4 v = make_float4(0.f, 0.f, 0.f, 0.f);
            if (gr < N) v = *(const float4*)(A + (size_t)gr * K + kc0 + a_kq);
            __half2 h01 = __float22half2_rn(make_float2(v.x, v.y));
            __half2 h23 = __float22half2_rn(make_float2(v.z, v.w));
            float2 f01 = __half22float2(h01);
            float2 f23 = __half22float2(h23);
            __half2 l01 = __float22half2_rn(make_float2(v.x - f01.x, v.y - f01.y));
            __half2 l23 = __float22half2_rn(make_float2(v.z - f23.x, v.w - f23.y));
            uint32_t off = (uint32_t)(m * AST + a_kq) * 2;
            *(__half2*)(smem + SMP_AHI + off)     = h01;
            *(__half2*)(smem + SMP_AHI + off + 4) = h23;
            *(__half2*)(smem + SMP_ALO + off)     = l01;
            *(__half2*)(smem + SMP_ALO + off + 4) = l23;
        }
#pragma unroll 8
        for (int j = 0; j < 32; j++) {
            int kk = bk0 + j;
            float w = W[(size_t)(kc0 + kk) * 128 + bn];
            __half h = __float2half_rn(w);
            __half l = __float2half_rn(w - __half2float(h));
            uint32_t off = (uint32_t)(bn * AST + kk) * 2;
            *(__half*)(smem + SMP_BHI + off) = h;
            *(__half*)(smem + SMP_BLO + off) = l;
        }
        __syncthreads();

#pragma unroll
        for (int ks = 0; ks < 4; ks++) {
            const int k0 = ks * 16;
            uint32_t ahr[8], alr[8];
#pragma unroll
            for (int t = 0; t < 2; t++) {
                int r0 = warp_r * 32 + t * 16 + gid;
                uint32_t o0 = (uint32_t)(r0 * AST + k0 + tig * 2) * 2;
                uint32_t o1 = (uint32_t)((r0 + 8) * AST + k0 + tig * 2) * 2;
                ahr[t * 4 + 0] = *(const uint32_t*)(smem + SMP_AHI + o0);
                ahr[t * 4 + 1] = *(const uint32_t*)(smem + SMP_AHI + o1);
                ahr[t * 4 + 2] = *(const uint32_t*)(smem + SMP_AHI + o0 + 16);
                ahr[t * 4 + 3] = *(const uint32_t*)(smem + SMP_AHI + o1 + 16);
                alr[t * 4 + 0] = *(const uint32_t*)(smem + SMP_ALO + o0);
                alr[t * 4 + 1] = *(const uint32_t*)(smem + SMP_ALO + o1);
                alr[t * 4 + 2] = *(const uint32_t*)(smem + SMP_ALO + o0 + 16);
                alr[t * 4 + 3] = *(const uint32_t*)(smem + SMP_ALO + o1 + 16);
            }
#pragma unroll
            for (int j = 0; j < 8; j++) {
                int n = warp_c * 64 + j * 8 + gid;
                uint32_t ob = (uint32_t)(n * AST + k0 + tig * 2) * 2;
                uint32_t bh0 = *(const uint32_t*)(smem + SMP_BHI + ob);
                uint32_t bh1 = *(const uint32_t*)(smem + SMP_BHI + ob + 16);
                uint32_t bl0 = *(const uint32_t*)(smem + SMP_BLO + ob);
                uint32_t bl1 = *(const uint32_t*)(smem + SMP_BLO + ob + 16);
#pragma unroll
                for (int t = 0; t < 2; t++) {
                    mma16816(acc[t][j], ahr + t * 4, bh0, bh1);
                    mma16816(acc[t][j], ahr + t * 4, bl0, bl1);
                    mma16816(acc[t][j], alr + t * 4, bh0, bh1);
                }
            }
        }
    }

    const float* bias_s = (const float*)(smem + SMP_BIAS);
#pragma unroll
    for (int t = 0; t < 2; t++) {
        int r_lo = row0 + warp_r * 32 + t * 16 + gid;
        int r_hi = r_lo + 8;
#pragma unroll
        for (int j = 0; j < 8; j++) {
            int col = warp_c * 64 + j * 8 + tig * 2;
            float bx = bias_s[col], by = bias_s[col + 1];
            if (r_lo < N) {
                __half2 h = __float22half2_rn(
                    make_float2(acc[t][j][0] + bx, acc[t][j][1] + by));
                *(__half2*)(Ch + (size_t)r_lo * 128 + col) = h;
            }
            if (r_hi < N) {
                __half2 h = __float22half2_rn(
                    make_float2(acc[t][j][2] + bx, acc[t][j][3] + by));
                *(__half2*)(Ch + (size_t)r_hi * 128 + col) = h;
            }
        }
    }
}

// ---------------- tensor-core SAGE GEMM (single direction) ---------------------
#define SMG_BIAS 0
#define SMG_A    1024
#define SMG_B    (SMG_A + 128 * AST * 2)
#define SMG_TOT  (SMG_B + 128 * AST * 2)

__global__ void __launch_bounds__(256, 2) sage_mma(
        int is_user, int cur, int mbuf,
        const __half* __restrict__ Wlt, const __half* __restrict__ Wrt,
        const float* __restrict__ bias) {
    extern __shared__ char smem[];
    const int tid = threadIdx.x;
    const int wid = tid >> 5;
    const int lane = tid & 31;

    const int tile = blockIdx.x;
    const __half* __restrict__ meanh = is_user ? mu(mbuf) : mb(mbuf);
    const __half* __restrict__ Xh    = is_user ? uh(cur) : bh(cur);
    __half* __restrict__ Oh          = is_user ? uh(cur ^ 1) : bh(cur ^ 1);
    const int N = is_user ? NU : NB;
    const int row0 = tile * 128;

    if (tid < 128) *(float*)(smem + SMG_BIAS + tid * 4) = bias[tid];

    const int warp_r = wid >> 1;
    const int warp_c = wid & 1;
    const int gid = lane >> 2;
    const int tig = lane & 3;

    float acc[2][8][4];
#pragma unroll
    for (int t = 0; t < 2; t++)
#pragma unroll
        for (int j = 0; j < 8; j++)
#pragma unroll
            for (int q = 0; q < 4; q++) acc[t][j][q] = 0.f;

    const int a_kq = (tid & 15) * 4;
    const int a_m0 = tid >> 4;
    const int bn = tid & 127;
    const int bk0 = (tid >> 7) * 32;

#pragma unroll 1
    for (int c = 0; c < 4; c++) {
        __syncthreads();

        const int kg0 = c * 64;
        const bool xpart = (kg0 >= 128);
        const __half* __restrict__ asrc = xpart ? Xh : meanh;
        const int akoff = xpart ? kg0 - 128 : kg0;
#pragma unroll
        for (int i = 0; i < 8; i++) {
            int m = a_m0 + i * 16;
            int gr = row0 + m;
            uint2 vh = make_uint2(0u, 0u);
            if (gr < N) vh = *(const uint2*)(asrc + (size_t)gr * 128 + akoff + a_kq);
            uint32_t off = (uint32_t)(m * AST + a_kq) * 2;
            *(uint2*)(smem + SMG_A + off) = vh;
        }

        const __half* __restrict__ wsrc = (xpart ? Wrt : Wlt) + (size_t)bn * 128
                                          + (xpart ? kg0 - 128 : kg0) + bk0;
#pragma unroll
        for (int j = 0; j < 4; j++) {
            uint4 v = *(const uint4*)(wsrc + j * 8);
            *(uint4*)(smem + SMG_B + (uint32_t)(bn * AST + bk0 + j * 8) * 2) = v;
        }
        __syncthreads();

#pragma unroll
        for (int ks = 0; ks < 4; ks++) {
            const int k0 = ks * 16;
            uint32_t ahr[8];
#pragma unroll
            for (int t = 0; t < 2; t++) {
                int r0 = warp_r * 32 + t * 16 + gid;
                uint32_t o0 = (uint32_t)(r0 * AST + k0 + tig * 2) * 2;
                uint32_t o1 = (uint32_t)((r0 + 8) * AST + k0 + tig * 2) * 2;
                ahr[t * 4 + 0] = *(const uint32_t*)(smem + SMG_A + o0);
                ahr[t * 4 + 1] = *(const uint32_t*)(smem + SMG_A + o1);
                ahr[t * 4 + 2] = *(const uint32_t*)(smem + SMG_A + o0 + 16);
                ahr[t * 4 + 3] = *(const uint32_t*)(smem + SMG_A + o1 + 16);
            }
#pragma unroll
            for (int j = 0; j < 8; j++) {
                int n = warp_c * 64 + j * 8 + gid;
                uint32_t ob = (uint32_t)(n * AST + k0 + tig * 2) * 2;
                uint32_t bh0 = *(const uint32_t*)(smem + SMG_B + ob);
                uint32_t bh1 = *(const uint32_t*)(smem + SMG_B + ob + 16);
#pragma unroll
                for (int t = 0; t < 2; t++)
                    mma16816(acc[t][j], ahr + t * 4, bh0, bh1);
            }
        }
    }

    const float* bias_s = (const float*)(smem + SMG_BIAS);
#pragma unroll
    for (int t = 0; t < 2; t++) {
        int r_lo = row0 + warp_r * 32 + t * 16 + gid;
        int r_hi = r_lo + 8;
#pragma unroll
        for (int j = 0; j < 8; j++) {
            int col = warp_c * 64 + j * 8 + tig * 2;
            float bx = bias_s[col], by = bias_s[col + 1];
            if (r_lo < N) {
                __half2 h = __float22half2_rn(make_float2(
                    fmaxf(acc[t][j][0] + bx, 0.f), fmaxf(acc[t][j][1] + by, 0.f)));
                *(__half2*)(Oh + (size_t)r_lo * 128 + col) = h;
            }
            if (r_hi < N) {
                __half2 h = __float22half2_rn(make_float2(
                    fmaxf(acc[t][j][2] + bx, 0.f), fmaxf(acc[t][j][3] + by, 0.f)));
                *(__half2*)(Oh + (size_t)r_hi * 128 + col) = h;
            }
        }
    }
}

// ---------------- layernorm (both populations, 1 warp / row) -------------------
__global__ void __launch_bounds__(256) ln_kernel(
        int cur,
        const float* __restrict__ ug, const float* __restrict__ ube,
        const float* __restrict__ bg, const float* __restrict__ bbe,
        float* __restrict__ out) {
    int gw   = (blockIdx.x * blockDim.x + threadIdx.x) >> 5;
    int lane = threadIdx.x & 31;
    if (gw >= NU + NB) return;

    int is_user = (gw < NU);
    int w = is_user ? gw : gw - NU;
    const __half* __restrict__ Xh = is_user ? uh(cur) : bh(cur);
    const float* gamma = is_user ? ug : bg;
    const float* beta  = is_user ? ube : bbe;
    float* op = out + (size_t)gw * 128;

    uint2 vh = *(const uint2*)(Xh + (size_t)w * 128 + lane * 4);
    float2 h0 = __half22float2(*(__half2*)&vh.x);
    float2 h1 = __half22float2(*(__half2*)&vh.y);
    float4 v;
    v.x = h0.x; v.y = h0.y; v.z = h1.x; v.w = h1.y;

    float s = v.x + v.y + v.z + v.w;
#pragma unroll
    for (int o = 16; o; o >>= 1) s += __shfl_xor_sync(0xffffffffu, s, o);
    float mean = s * (1.0f / 128.0f);

    float dx = v.x - mean, dy = v.y - mean, dz = v.z - mean, dw = v.w - mean;
    float q = dx * dx + dy * dy + dz * dz + dw * dw;
#pragma unroll
    for (int o = 16; o; o >>= 1) q += __shfl_xor_sync(0xffffffffu, q, o);
    float rs = rsqrtf(q * (1.0f / 128.0f) + 1e-5f);

    float4 g  = *(const float4*)(gamma + lane * 4);
    float4 bt = *(const float4*)(beta + lane * 4);
    float4 o4;
    o4.x = dx * rs * g.x + bt.x;
    o4.y = dy * rs * g.y + bt.y;
    o4.z = dz * rs * g.z + bt.z;
    o4.w = dw * rs * g.w + bt.w;
    *(float4*)(op + lane * 4) = o4;
}

// ---------------- launch --------------------------------------------------------
extern "C" void kernel_launch(void* const* d_in, const int* in_sizes, int n_in,
                              void* d_out, int out_size) {
    const float* user_x = (const float*)d_in[0];
    const float* book_x = (const float*)d_in[1];
    const int*   esrc   = (const int*)d_in[2];
    const int*   edst   = (const int*)d_in[3];
    const float* upw    = (const float*)d_in[4];
    const float* upb    = (const float*)d_in[5];
    const float* bpw    = (const float*)d_in[6];
    const float* bpb    = (const float*)d_in[7];
    const float* Wl     = (const float*)d_in[8];
    const float* bl_    = (const float*)d_in[9];
    const float* Wr     = (const float*)d_in[10];
    const float* ug     = (const float*)d_in[11];
    const float* ube    = (const float*)d_in[12];
    const float* bg     = (const float*)d_in[13];
    const float* bbe    = (const float*)d_in[14];
    float* out = (float*)d_out;

    (void)in_sizes; (void)n_in; (void)out_size;

    // one-time host-side setup (streams/events; no device memory)
    static cudaStream_t sB = 0, sU = 0;
    static cudaEvent_t evIn = 0, evProj = 0, evBuild = 0;
    static cudaEvent_t evSb[3], evSu[3], evLn0, evLn1;
    if (!sB) {
        cudaStreamCreateWithFlags(&sB, cudaStreamNonBlocking);
        cudaStreamCreateWithFlags(&sU, cudaStreamNonBlocking);
        cudaEventCreateWithFlags(&evIn, cudaEventDisableTiming);
        cudaEventCreateWithFlags(&evProj, cudaEventDisableTiming);
        cudaEventCreateWithFlags(&evBuild, cudaEventDisableTiming);
        for (int i = 0; i < 3; i++) {
            cudaEventCreateWithFlags(&evSb[i], cudaEventDisableTiming);
            cudaEventCreateWithFlags(&evSu[i], cudaEventDisableTiming);
        }
        cudaEventCreateWithFlags(&evLn0, cudaEventDisableTiming);
        cudaEventCreateWithFlags(&evLn1, cudaEventDisableTiming);
    }

    cudaFuncSetAttribute(proj_mma, cudaFuncAttributeMaxDynamicSharedMemorySize, SMP_TOT);
    cudaFuncSetAttribute(sage_mma, cudaFuncAttributeMaxDynamicSharedMemorySize, SMG_TOT);

    int* d_offs_u; cudaGetSymbolAddress((void**)&d_offs_u, g_offs_u);
    int* d_offs_b; cudaGetSymbolAddress((void**)&d_offs_b, g_offs_b);
    int* d_deg_u;  cudaGetSymbolAddress((void**)&d_deg_u,  g_deg_u);
    int* d_deg_b;  cudaGetSymbolAddress((void**)&d_deg_b,  g_deg_b);
    int* d_bsum_u; cudaGetSymbolAddress((void**)&d_bsum_u, g_bsum_u);
    int* d_bsum_b; cudaGetSymbolAddress((void**)&d_bsum_b, g_bsum_b);
    int* d_cur_u;  cudaGetSymbolAddress((void**)&d_cur_u,  g_cur_u);
    int* d_cur_b;  cudaGetSymbolAddress((void**)&d_cur_b,  g_cur_b);
    __half* d_wlt; cudaGetSymbolAddress((void**)&d_wlt, g_wlt);
    __half* d_wrt; cudaGetSymbolAddress((void**)&d_wrt, g_wrt);

    // ---- fork: proj chain on sB, CSR build on default stream ----
    cudaEventRecord(evIn, 0);
    cudaStreamWaitEvent(sB, evIn, 0);
    convert_w<<<(3 * 16384 + 255) / 256, 256, 0, sB>>>(Wl, Wr);
    proj_mma<<<TU + TB, 256, SMP_TOT, sB>>>(user_x, book_x, upw, upb, bpw, bpb);
    cudaEventRecord(evProj, sB);

    cudaMemsetAsync(d_deg_u, 0, NU * sizeof(int), 0);
    cudaMemsetAsync(d_deg_b, 0, NB * sizeof(int), 0);
    deg_kernel<<<(NE + 255) / 256, 256>>>(esrc, edst);
    scan_blocks<<<NBLK_U, 1024>>>(d_deg_u, d_offs_u, d_bsum_u, NU);
    scan_blocks<<<NBLK_B, 1024>>>(d_deg_b, d_offs_b, d_bsum_b, NB);
    scan_small<<<1, 256>>>(d_bsum_u, NBLK_U);
    scan_small<<<1, 256>>>(d_bsum_b, NBLK_B);
    scan_add<<<(NU + 255) / 256, 256>>>(d_offs_u, d_bsum_u, d_cur_u, NU, NBLK_U);
    scan_add<<<(NB + 255) / 256, 256>>>(d_offs_b, d_bsum_b, d_cur_b, NB, NBLK_B);
    fill_kernel<<<(NE + 255) / 256, 256>>>(esrc, edst);
    cudaEventRecord(evBuild, 0);

    cudaStreamWaitEvent(sB, evBuild, 0);
    cudaStreamWaitEvent(sU, evBuild, 0);
    cudaStreamWaitEvent(sU, evProj, 0);

    // ---- pipelined direction chains: book chain on sB, user chain on sU ----
    const int GBB = (int)(((size_t)NB * 32 + 255) / 256);
    const int GBU = (int)(((size_t)NU * 32 + 255) / 256);
    int cur = 0;
    for (int l = 0; l < 3; l++) {
        const __half* wlt = d_wlt + (size_t)l * 16384;
        const __half* wrt = d_wrt + (size_t)l * 16384;
        const float* bb = bl_ + (size_t)l * 128;

        if (l > 0) cudaStreamWaitEvent(sB, evSu[l - 1], 0);   // Gb(l) reads uh <- Su(l-1)
        gather_mean<<<GBB, 256, 0, sB>>>(0, cur, l & 1);
        sage_mma<<<TB, 256, SMG_TOT, sB>>>(0, cur, l & 1, wlt, wrt, bb);
        cudaEventRecord(evSb[l], sB);

        if (l > 0) cudaStreamWaitEvent(sU, evSb[l - 1], 0);   // Gu(l) reads bh <- Sb(l-1)
        gather_mean<<<GBU, 256, 0, sU>>>(1, cur, l & 1);
        sage_mma<<<TU, 256, SMG_TOT, sU>>>(1, cur, l & 1, wlt, wrt, bb);
        cudaEventRecord(evSu[l], sU);

        cur ^= 1;
    }

    // ---- join on default stream, then layernorm ----
    cudaStreamWaitEvent(0, evSb[2], 0);
    cudaStreamWaitEvent(0, evSu[2], 0);
    ln_kernel<<<(int)(((size_t)(NU + NB) * 32 + 255) / 256), 256>>>(
        cur, ug, ube, bg, bbe, out);
}